// round 3
// baseline (speedup 1.0000x reference)
#include <cuda_runtime.h>
#include <cuda_bf16.h>
#include <math.h>

// Problem dims (fixed)
#define BB 2
#define TT 2048
#define CC 1024
#define HH 16
#define HD 64
#define NROWS (BB*TT)          // 4096
#define FF (4*CC)              // 4096

// ---------------- scratch (allocation-free rule: __device__ globals) --------
__device__ float g_h [NROWS*CC];   // LN1 out, later reused for attention output y
__device__ float g_q [NROWS*CC];   // q, later reused for h2 (LN2 out)
__device__ float g_k [NROWS*CC];
__device__ float g_v [NROWS*CC];
__device__ float g_x1[NROWS*CC];   // x after attention residual
__device__ float g_m [NROWS*FF];   // MLP hidden

// ---------------- LayerNorm ----------------
__global__ __launch_bounds__(256)
void ln_kernel(const float* __restrict__ x, const float* __restrict__ w,
               const float* __restrict__ b, float* __restrict__ out)
{
    __shared__ float red[16];
    const int row = blockIdx.x;
    const int t = threadIdx.x;                 // 256 threads, 1 float4 each (C=1024)
    const float4* xr = (const float4*)(x + (size_t)row * CC);
    float4 v = xr[t];
    float s  = v.x + v.y + v.z + v.w;
    float ss = v.x*v.x + v.y*v.y + v.z*v.z + v.w*v.w;
    #pragma unroll
    for (int off = 16; off >= 1; off >>= 1) {
        s  += __shfl_xor_sync(0xffffffffu, s,  off);
        ss += __shfl_xor_sync(0xffffffffu, ss, off);
    }
    const int wid = t >> 5, lane = t & 31;
    if (lane == 0) { red[wid] = s; red[8 + wid] = ss; }
    __syncthreads();
    if (t == 0) {
        float S = 0.f, SS = 0.f;
        #pragma unroll
        for (int i = 0; i < 8; i++) { S += red[i]; SS += red[8 + i]; }
        red[0] = S; red[1] = SS;
    }
    __syncthreads();
    const float mu  = red[0] * (1.0f / CC);
    const float var = red[1] * (1.0f / CC) - mu * mu;
    const float rstd = rsqrtf(var + 1e-5f);
    const float4 wv = ((const float4*)w)[t];
    const float4 bv = ((const float4*)b)[t];
    float4 o;
    o.x = (v.x - mu) * rstd * wv.x + bv.x;
    o.y = (v.y - mu) * rstd * wv.y + bv.y;
    o.z = (v.z - mu) * rstd * wv.z + bv.z;
    o.w = (v.w - mu) * rstd * wv.w + bv.w;
    ((float4*)(out + (size_t)row * CC))[t] = o;
}

// ---------------- GEMM: out[M,N] = A[M,K] @ W[N,K]^T + bias (+gelu)(+res) ---
__device__ __forceinline__ float gelu_exact(float v) {
    return 0.5f * v * (1.0f + erff(v * 0.70710678118654752f));
}

template<int ACT, bool RES>
__global__ __launch_bounds__(256, 2)
void gemm_kernel(const float* __restrict__ A, const float* __restrict__ W,
                 const float* __restrict__ bias, const float* __restrict__ res,
                 float* __restrict__ out, int M, int N, int K)
{
    __shared__ float As[8][128];
    __shared__ float Bs[8][128];
    const int t = threadIdx.x;
    const int m0 = blockIdx.y * 128;
    const int n0 = blockIdx.x * 128;
    const int lr = t >> 1;               // 0..127
    const int lk = (t & 1) * 4;          // 0 or 4
    const float* aptr = A + (size_t)(m0 + lr) * K + lk;
    const float* bptr = W + (size_t)(n0 + lr) * K + lk;
    const int ty = t >> 4;               // 0..15  (8 rows each)
    const int tx = t & 15;               // 0..15  (8 cols each)

    float acc[8][8];
    #pragma unroll
    for (int i = 0; i < 8; i++)
        #pragma unroll
        for (int j = 0; j < 8; j++) acc[i][j] = 0.f;

    for (int k0 = 0; k0 < K; k0 += 8) {
        const float4 av = *(const float4*)(aptr + k0);
        const float4 bv = *(const float4*)(bptr + k0);
        __syncthreads();
        As[lk + 0][lr] = av.x; As[lk + 1][lr] = av.y;
        As[lk + 2][lr] = av.z; As[lk + 3][lr] = av.w;
        Bs[lk + 0][lr] = bv.x; Bs[lk + 1][lr] = bv.y;
        Bs[lk + 2][lr] = bv.z; Bs[lk + 3][lr] = bv.w;
        __syncthreads();
        #pragma unroll
        for (int kk = 0; kk < 8; kk++) {
            const float4 a0 = *(const float4*)&As[kk][ty * 8];
            const float4 a1 = *(const float4*)&As[kk][ty * 8 + 4];
            const float4 b0 = *(const float4*)&Bs[kk][tx * 8];
            const float4 b1 = *(const float4*)&Bs[kk][tx * 8 + 4];
            const float ar[8] = {a0.x,a0.y,a0.z,a0.w,a1.x,a1.y,a1.z,a1.w};
            const float br[8] = {b0.x,b0.y,b0.z,b0.w,b1.x,b1.y,b1.z,b1.w};
            #pragma unroll
            for (int i = 0; i < 8; i++)
                #pragma unroll
                for (int j = 0; j < 8; j++)
                    acc[i][j] += ar[i] * br[j];
        }
    }

    float bc[8];
    #pragma unroll
    for (int j = 0; j < 8; j++) bc[j] = bias[n0 + tx * 8 + j];

    #pragma unroll
    for (int i = 0; i < 8; i++) {
        const size_t r = (size_t)(m0 + ty * 8 + i);
        float* orow = out + r * N + n0 + tx * 8;
        const float* rrow = RES ? (res + r * N + n0 + tx * 8) : nullptr;
        float vout[8];
        #pragma unroll
        for (int j = 0; j < 8; j++) {
            float v = acc[i][j] + bc[j];
            if (ACT == 1) v = gelu_exact(v);
            if (RES) v += rrow[j];
            vout[j] = v;
        }
        *(float4*)(orow + 0) = make_float4(vout[0], vout[1], vout[2], vout[3]);
        *(float4*)(orow + 4) = make_float4(vout[4], vout[5], vout[6], vout[7]);
    }
}

// ---------------- Flash attention (fp32, causal, HD=64, BQ=BKV=64) ----------
__global__ __launch_bounds__(256)
void attn_kernel(const float* __restrict__ q, const float* __restrict__ k,
                 const float* __restrict__ v, float* __restrict__ y)
{
    __shared__ float Qs [64 * 64];   // [d][row]  (scaled Q, transposed)
    __shared__ float KVs[64 * 64];   // phase A: K as [d][key]; phase B: V as [kv][d]
    __shared__ float Ps [64 * 64];   // [row][kv]

    const int bh = blockIdx.x;
    const int b  = bh >> 4;
    const int h  = bh & 15;
    const int it = gridDim.y - 1 - blockIdx.y;   // heavy (diagonal-far) tiles first
    const int t  = threadIdx.x;
    const int tr = t >> 4;           // 0..15 -> 4 q-rows each
    const int tc = t & 15;           // 0..15 -> 4 cols each
    const float scale = 0.125f;      // 1/sqrt(64)

    // load Q tile transposed+scaled: 256 threads, 16 elements each
    {
        const int row = t >> 2;
        const int dg  = (t & 3) * 16;
        const float* src = q + (size_t)(b * TT + it * 64 + row) * CC + h * HD + dg;
        #pragma unroll
        for (int j = 0; j < 4; j++) {
            const float4 vv = *(const float4*)(src + 4 * j);
            Qs[(dg + 4*j + 0) * 64 + row] = vv.x * scale;
            Qs[(dg + 4*j + 1) * 64 + row] = vv.y * scale;
            Qs[(dg + 4*j + 2) * 64 + row] = vv.z * scale;
            Qs[(dg + 4*j + 3) * 64 + row] = vv.w * scale;
        }
    }

    float o[4][4];
    #pragma unroll
    for (int i = 0; i < 4; i++)
        #pragma unroll
        for (int j = 0; j < 4; j++) o[i][j] = 0.f;
    float mrow[4] = {-INFINITY, -INFINITY, -INFINITY, -INFINITY};
    float lrow[4] = {0.f, 0.f, 0.f, 0.f};

    for (int jt = 0; jt <= it; jt++) {
        __syncthreads();  // previous O-phase done (and Q load visible on iter 0 path)
        // load K tile transposed: KVs[d][key]
        {
            const int row = t >> 2;
            const int dg  = (t & 3) * 16;
            const float* src = k + (size_t)(b * TT + jt * 64 + row) * CC + h * HD + dg;
            #pragma unroll
            for (int j = 0; j < 4; j++) {
                const float4 vv = *(const float4*)(src + 4 * j);
                KVs[(dg + 4*j + 0) * 64 + row] = vv.x;
                KVs[(dg + 4*j + 1) * 64 + row] = vv.y;
                KVs[(dg + 4*j + 2) * 64 + row] = vv.z;
                KVs[(dg + 4*j + 3) * 64 + row] = vv.w;
            }
        }
        __syncthreads();

        // S = Q @ K^T (4x4 per thread)
        float s[4][4];
        #pragma unroll
        for (int i = 0; i < 4; i++)
            #pragma unroll
            for (int j = 0; j < 4; j++) s[i][j] = 0.f;
        #pragma unroll 8
        for (int d = 0; d < 64; d++) {
            const float4 a = *(const float4*)&Qs [d * 64 + tr * 4];
            const float4 c = *(const float4*)&KVs[d * 64 + tc * 4];
            const float ar[4] = {a.x, a.y, a.z, a.w};
            const float cr[4] = {c.x, c.y, c.z, c.w};
            #pragma unroll
            for (int i = 0; i < 4; i++)
                #pragma unroll
                for (int j = 0; j < 4; j++)
                    s[i][j] += ar[i] * cr[j];
        }

        // causal mask on diagonal tile
        if (jt == it) {
            #pragma unroll
            for (int i = 0; i < 4; i++)
                #pragma unroll
                for (int j = 0; j < 4; j++)
                    if (tc * 4 + j > tr * 4 + i) s[i][j] = -1e30f;
        }

        // online softmax update (row reduction across the 16 tc-lanes)
        #pragma unroll
        for (int i = 0; i < 4; i++) {
            float mx = fmaxf(fmaxf(s[i][0], s[i][1]), fmaxf(s[i][2], s[i][3]));
            #pragma unroll
            for (int off = 8; off >= 1; off >>= 1)
                mx = fmaxf(mx, __shfl_xor_sync(0xffffffffu, mx, off));
            const float mn = fmaxf(mrow[i], mx);
            const float corr = __expf(mrow[i] - mn);   // 0 when mrow = -inf
            mrow[i] = mn;
            float rs = 0.f;
            #pragma unroll
            for (int j = 0; j < 4; j++) {
                s[i][j] = __expf(s[i][j] - mn);
                rs += s[i][j];
            }
            #pragma unroll
            for (int off = 8; off >= 1; off >>= 1)
                rs += __shfl_xor_sync(0xffffffffu, rs, off);
            lrow[i] = lrow[i] * corr + rs;
            #pragma unroll
            for (int j = 0; j < 4; j++) o[i][j] *= corr;
            *(float4*)&Ps[(tr * 4 + i) * 64 + tc * 4] =
                make_float4(s[i][0], s[i][1], s[i][2], s[i][3]);
        }
        __syncthreads();  // S-phase reads of K done; P visible

        // load V tile natural: KVs[kv][d]
        {
            const int row = t >> 2;
            const int dg  = (t & 3) * 16;
            const float* src = v + (size_t)(b * TT + jt * 64 + row) * CC + h * HD + dg;
            #pragma unroll
            for (int j = 0; j < 4; j++)
                *(float4*)&KVs[row * 64 + dg + 4 * j] = *(const float4*)(src + 4 * j);
        }
        __syncthreads();

        // O += P @ V
        #pragma unroll 4
        for (int kv = 0; kv < 64; kv += 4) {
            float p[4][4];
            #pragma unroll
            for (int i = 0; i < 4; i++) {
                const float4 pv = *(const float4*)&Ps[(tr * 4 + i) * 64 + kv];
                p[i][0] = pv.x; p[i][1] = pv.y; p[i][2] = pv.z; p[i][3] = pv.w;
            }
            #pragma unroll
            for (int u = 0; u < 4; u++) {
                const float4 vv = *(const float4*)&KVs[(kv + u) * 64 + tc * 4];
                #pragma unroll
                for (int i = 0; i < 4; i++) {
                    o[i][0] += p[i][u] * vv.x;
                    o[i][1] += p[i][u] * vv.y;
                    o[i][2] += p[i][u] * vv.z;
                    o[i][3] += p[i][u] * vv.w;
                }
            }
        }
    }

    // finalize + write y (B,T,C layout)
    #pragma unroll
    for (int i = 0; i < 4; i++) {
        const float inv = 1.0f / lrow[i];
        float* dst = y + (size_t)(b * TT + it * 64 + tr * 4 + i) * CC + h * HD + tc * 4;
        *(float4*)dst = make_float4(o[i][0]*inv, o[i][1]*inv, o[i][2]*inv, o[i][3]*inv);
    }
}

// ---------------- launch ----------------
extern "C" void kernel_launch(void* const* d_in, const int* in_sizes, int n_in,
                              void* d_out, int out_size)
{
    (void)in_sizes; (void)n_in; (void)out_size;
    const float* x     = (const float*)d_in[0];
    const float* ln1_w = (const float*)d_in[1];
    const float* ln1_b = (const float*)d_in[2];
    const float* ln2_w = (const float*)d_in[3];
    const float* ln2_b = (const float*)d_in[4];
    const float* Wq    = (const float*)d_in[5];
    const float* bq    = (const float*)d_in[6];
    const float* Wk    = (const float*)d_in[7];
    const float* bk    = (const float*)d_in[8];
    const float* Wv    = (const float*)d_in[9];
    const float* bv    = (const float*)d_in[10];
    const float* Wp    = (const float*)d_in[11];
    const float* bp    = (const float*)d_in[12];
    const float* W1    = (const float*)d_in[13];
    const float* b1    = (const float*)d_in[14];
    const float* W2    = (const float*)d_in[15];
    const float* b2    = (const float*)d_in[16];
    float* out = (float*)d_out;

    float *h, *q, *k, *v, *x1, *m;
    cudaGetSymbolAddress((void**)&h,  g_h);
    cudaGetSymbolAddress((void**)&q,  g_q);
    cudaGetSymbolAddress((void**)&k,  g_k);
    cudaGetSymbolAddress((void**)&v,  g_v);
    cudaGetSymbolAddress((void**)&x1, g_x1);
    cudaGetSymbolAddress((void**)&m,  g_m);

    // 1) h = LN1(x)
    ln_kernel<<<NROWS, 256>>>(x, ln1_w, ln1_b, h);
    // 2) q,k,v = h @ W{q,k,v}^T + b
    gemm_kernel<0,false><<<dim3(CC/128, NROWS/128), 256>>>(h, Wq, bq, nullptr, q, NROWS, CC, CC);
    gemm_kernel<0,false><<<dim3(CC/128, NROWS/128), 256>>>(h, Wk, bk, nullptr, k, NROWS, CC, CC);
    gemm_kernel<0,false><<<dim3(CC/128, NROWS/128), 256>>>(h, Wv, bv, nullptr, v, NROWS, CC, CC);
    // 3) y = causal-attention(q,k,v)  (written into h, which is free now)
    attn_kernel<<<dim3(BB*HH, TT/64), 256>>>(q, k, v, h);
    // 4) x1 = x + y @ Wp^T + bp
    gemm_kernel<0,true><<<dim3(CC/128, NROWS/128), 256>>>(h, Wp, bp, x, x1, NROWS, CC, CC);
    // 5) h2 = LN2(x1)  (into q, free now)
    ln_kernel<<<NROWS, 256>>>(x1, ln2_w, ln2_b, q);
    // 6) m = gelu(h2 @ W1^T + b1)
    gemm_kernel<1,false><<<dim3(FF/128, NROWS/128), 256>>>(q, W1, b1, nullptr, m, NROWS, FF, CC);
    // 7) out = x1 + m @ W2^T + b2
    gemm_kernel<0,true><<<dim3(CC/128, NROWS/128), 256>>>(m, W2, b2, x1, out, NROWS, CC, FF);
}

// round 4
// speedup vs baseline: 3.8612x; 3.8612x over previous
#include <cuda_runtime.h>
#include <cuda_bf16.h>
#include <math.h>
#include <stdint.h>

// Problem dims (fixed)
#define BB 2
#define TT 2048
#define CC 1024
#define HH 16
#define HD 64
#define NROWS (BB*TT)          // 4096
#define FF (4*CC)              // 4096

// ---------------- scratch (allocation-free rule: __device__ globals) --------
__device__ float g_h [NROWS*CC];   // LN1 out, later reused for attention output y
__device__ float g_q [NROWS*CC];   // q, later reused for h2 (LN2 out)
__device__ float g_k [NROWS*CC];
__device__ float g_v [NROWS*CC];
__device__ float g_x1[NROWS*CC];   // x after attention residual
__device__ float g_m [NROWS*FF];   // MLP hidden

// ---------------- LayerNorm ----------------
__global__ __launch_bounds__(256)
void ln_kernel(const float* __restrict__ x, const float* __restrict__ w,
               const float* __restrict__ b, float* __restrict__ out)
{
    __shared__ float red[16];
    const int row = blockIdx.x;
    const int t = threadIdx.x;
    const float4* xr = (const float4*)(x + (size_t)row * CC);
    float4 v = xr[t];
    float s  = v.x + v.y + v.z + v.w;
    float ss = v.x*v.x + v.y*v.y + v.z*v.z + v.w*v.w;
    #pragma unroll
    for (int off = 16; off >= 1; off >>= 1) {
        s  += __shfl_xor_sync(0xffffffffu, s,  off);
        ss += __shfl_xor_sync(0xffffffffu, ss, off);
    }
    const int wid = t >> 5, lane = t & 31;
    if (lane == 0) { red[wid] = s; red[8 + wid] = ss; }
    __syncthreads();
    if (t == 0) {
        float S = 0.f, SS = 0.f;
        #pragma unroll
        for (int i = 0; i < 8; i++) { S += red[i]; SS += red[8 + i]; }
        red[0] = S; red[1] = SS;
    }
    __syncthreads();
    const float mu  = red[0] * (1.0f / CC);
    const float var = red[1] * (1.0f / CC) - mu * mu;
    const float rstd = rsqrtf(var + 1e-5f);
    const float4 wv = ((const float4*)w)[t];
    const float4 bv = ((const float4*)b)[t];
    float4 o;
    o.x = (v.x - mu) * rstd * wv.x + bv.x;
    o.y = (v.y - mu) * rstd * wv.y + bv.y;
    o.z = (v.z - mu) * rstd * wv.z + bv.z;
    o.w = (v.w - mu) * rstd * wv.w + bv.w;
    ((float4*)(out + (size_t)row * CC))[t] = o;
}

// ---------------- helpers ----------------
__device__ __forceinline__ float gelu_exact(float v) {
    return 0.5f * v * (1.0f + erff(v * 0.70710678118654752f));
}
__device__ __forceinline__ uint32_t f2tf(float x) {
    uint32_t r; asm("cvt.rna.tf32.f32 %0, %1;" : "=r"(r) : "f"(x)); return r;
}
__device__ __forceinline__ void mma16x8x8(float c[4], const uint32_t a[4], const uint32_t b[2]) {
    asm volatile("mma.sync.aligned.m16n8k8.row.col.f32.tf32.tf32.f32 "
        "{%0,%1,%2,%3}, {%4,%5,%6,%7}, {%8,%9}, {%0,%1,%2,%3};\n"
        : "+f"(c[0]), "+f"(c[1]), "+f"(c[2]), "+f"(c[3])
        : "r"(a[0]), "r"(a[1]), "r"(a[2]), "r"(a[3]), "r"(b[0]), "r"(b[1]));
}
__device__ __forceinline__ void cp16(uint32_t s, const float* g) {
    asm volatile("cp.async.ca.shared.global [%0], [%1], 16;\n" :: "r"(s), "l"(g));
}

// ---------------- tf32 tensor-core GEMM ----------------
// out[M,N] = A[M,K] @ W[N,K]^T + bias (+gelu)(+res)
#define BM 128
#define BN 128
#define BK 16
#define LDSK 20   // padded k-stride (floats): conflict-free fragment loads

template<int ACT, bool RES>
__global__ __launch_bounds__(256, 2)
void gemm_tf32(const float* __restrict__ A, const float* __restrict__ W,
               const float* __restrict__ bias, const float* __restrict__ res,
               float* __restrict__ out, int M, int N, int K)
{
    __shared__ float As[2][BM * LDSK];
    __shared__ float Bs[2][BN * LDSK];

    const int t = threadIdx.x;
    const int wid  = t >> 5;
    const int lane = t & 31;
    const int g    = lane >> 2;       // 0..7
    const int tig  = lane & 3;        // 0..3
    const int wm = (wid & 1) * 64;    // warp m-offset in tile
    const int wn = (wid >> 1) * 32;   // warp n-offset in tile
    const int m0 = blockIdx.y * BM;
    const int n0 = blockIdx.x * BN;

    // loader: each thread owns row lr, half kh; 2x float4 per operand per tile
    const int lr = t >> 1;            // 0..127
    const int kh = (t & 1) * 8;       // 0 or 8
    const float* ag = A + (size_t)(m0 + lr) * K + kh;
    const float* bg = W + (size_t)(n0 + lr) * K + kh;
    const uint32_t as_s = (uint32_t)__cvta_generic_to_shared(&As[0][lr * LDSK + kh]);
    const uint32_t bs_s = (uint32_t)__cvta_generic_to_shared(&Bs[0][lr * LDSK + kh]);
    const uint32_t bufbytes = BM * LDSK * 4;

    float acc[4][4][4];
    #pragma unroll
    for (int mt = 0; mt < 4; mt++)
        #pragma unroll
        for (int nt = 0; nt < 4; nt++)
            #pragma unroll
            for (int r = 0; r < 4; r++) acc[mt][nt][r] = 0.f;

    const int KT = K / BK;
    // prologue: stage tile 0 into buffer 0
    cp16(as_s, ag);      cp16(as_s + 16, ag + 4);
    cp16(bs_s, bg);      cp16(bs_s + 16, bg + 4);
    asm volatile("cp.async.commit_group;\n");

    for (int kt = 0; kt < KT; ++kt) {
        if (kt + 1 < KT) {
            const float* ag2 = ag + (size_t)(kt + 1) * BK;
            const float* bg2 = bg + (size_t)(kt + 1) * BK;
            const uint32_t off = ((kt + 1) & 1) * bufbytes;
            cp16(as_s + off, ag2);      cp16(as_s + off + 16, ag2 + 4);
            cp16(bs_s + off, bg2);      cp16(bs_s + off + 16, bg2 + 4);
            asm volatile("cp.async.commit_group;\n");
            asm volatile("cp.async.wait_group 1;\n");
        } else {
            asm volatile("cp.async.wait_group 0;\n");
        }
        __syncthreads();
        const float* Ab = As[kt & 1];
        const float* Bb = Bs[kt & 1];
        #pragma unroll
        for (int ks = 0; ks < 2; ++ks) {
            const int k0 = ks * 8;
            uint32_t af[4][4], bf[4][2];
            #pragma unroll
            for (int mt = 0; mt < 4; ++mt) {
                const float* p = Ab + (wm + mt * 16 + g) * LDSK + k0 + tig;
                af[mt][0] = f2tf(p[0]);
                af[mt][1] = f2tf(p[8 * LDSK]);
                af[mt][2] = f2tf(p[4]);
                af[mt][3] = f2tf(p[8 * LDSK + 4]);
            }
            #pragma unroll
            for (int nt = 0; nt < 4; ++nt) {
                const float* p = Bb + (wn + nt * 8 + g) * LDSK + k0 + tig;
                bf[nt][0] = f2tf(p[0]);
                bf[nt][1] = f2tf(p[4]);
            }
            #pragma unroll
            for (int mt = 0; mt < 4; ++mt)
                #pragma unroll
                for (int nt = 0; nt < 4; ++nt)
                    mma16x8x8(acc[mt][nt], af[mt], bf[nt]);
        }
        __syncthreads();
    }

    // epilogue: c0/c1 at (row g, cols 2tig..2tig+1), c2/c3 at row g+8
    #pragma unroll
    for (int nt = 0; nt < 4; ++nt) {
        const int col = n0 + wn + nt * 8 + 2 * tig;
        const float2 bc = *(const float2*)(bias + col);
        #pragma unroll
        for (int mt = 0; mt < 4; ++mt) {
            const int row = m0 + wm + mt * 16 + g;
            float v0 = acc[mt][nt][0] + bc.x;
            float v1 = acc[mt][nt][1] + bc.y;
            float v2 = acc[mt][nt][2] + bc.x;
            float v3 = acc[mt][nt][3] + bc.y;
            if (ACT == 1) {
                v0 = gelu_exact(v0); v1 = gelu_exact(v1);
                v2 = gelu_exact(v2); v3 = gelu_exact(v3);
            }
            if (RES) {
                const float2 r0 = *(const float2*)(res + (size_t)row * N + col);
                const float2 r1 = *(const float2*)(res + (size_t)(row + 8) * N + col);
                v0 += r0.x; v1 += r0.y; v2 += r1.x; v3 += r1.y;
            }
            *(float2*)(out + (size_t)row * N + col)       = make_float2(v0, v1);
            *(float2*)(out + (size_t)(row + 8) * N + col) = make_float2(v2, v3);
        }
    }
}

// ---------------- Flash attention (fp32, causal, HD=64, BQ=BKV=64) ----------
__global__ __launch_bounds__(256)
void attn_kernel(const float* __restrict__ q, const float* __restrict__ k,
                 const float* __restrict__ v, float* __restrict__ y)
{
    __shared__ float Qs [64 * 64];   // [d][row]  (scaled Q, transposed)
    __shared__ float KVs[64 * 64];   // phase A: K as [d][key]; phase B: V as [kv][d]
    __shared__ float Ps [64 * 64];   // [row][kv]

    const int bh = blockIdx.x;
    const int b  = bh >> 4;
    const int h  = bh & 15;
    const int it = gridDim.y - 1 - blockIdx.y;
    const int t  = threadIdx.x;
    const int tr = t >> 4;
    const int tc = t & 15;
    const float scale = 0.125f;

    {
        const int row = t >> 2;
        const int dg  = (t & 3) * 16;
        const float* src = q + (size_t)(b * TT + it * 64 + row) * CC + h * HD + dg;
        #pragma unroll
        for (int j = 0; j < 4; j++) {
            const float4 vv = *(const float4*)(src + 4 * j);
            Qs[(dg + 4*j + 0) * 64 + row] = vv.x * scale;
            Qs[(dg + 4*j + 1) * 64 + row] = vv.y * scale;
            Qs[(dg + 4*j + 2) * 64 + row] = vv.z * scale;
            Qs[(dg + 4*j + 3) * 64 + row] = vv.w * scale;
        }
    }

    float o[4][4];
    #pragma unroll
    for (int i = 0; i < 4; i++)
        #pragma unroll
        for (int j = 0; j < 4; j++) o[i][j] = 0.f;
    float mrow[4] = {-INFINITY, -INFINITY, -INFINITY, -INFINITY};
    float lrow[4] = {0.f, 0.f, 0.f, 0.f};

    for (int jt = 0; jt <= it; jt++) {
        __syncthreads();
        {
            const int row = t >> 2;
            const int dg  = (t & 3) * 16;
            const float* src = k + (size_t)(b * TT + jt * 64 + row) * CC + h * HD + dg;
            #pragma unroll
            for (int j = 0; j < 4; j++) {
                const float4 vv = *(const float4*)(src + 4 * j);
                KVs[(dg + 4*j + 0) * 64 + row] = vv.x;
                KVs[(dg + 4*j + 1) * 64 + row] = vv.y;
                KVs[(dg + 4*j + 2) * 64 + row] = vv.z;
                KVs[(dg + 4*j + 3) * 64 + row] = vv.w;
            }
        }
        __syncthreads();

        float s[4][4];
        #pragma unroll
        for (int i = 0; i < 4; i++)
            #pragma unroll
            for (int j = 0; j < 4; j++) s[i][j] = 0.f;
        #pragma unroll 8
        for (int d = 0; d < 64; d++) {
            const float4 a = *(const float4*)&Qs [d * 64 + tr * 4];
            const float4 c = *(const float4*)&KVs[d * 64 + tc * 4];
            const float ar[4] = {a.x, a.y, a.z, a.w};
            const float cr[4] = {c.x, c.y, c.z, c.w};
            #pragma unroll
            for (int i = 0; i < 4; i++)
                #pragma unroll
                for (int j = 0; j < 4; j++)
                    s[i][j] += ar[i] * cr[j];
        }

        if (jt == it) {
            #pragma unroll
            for (int i = 0; i < 4; i++)
                #pragma unroll
                for (int j = 0; j < 4; j++)
                    if (tc * 4 + j > tr * 4 + i) s[i][j] = -1e30f;
        }

        #pragma unroll
        for (int i = 0; i < 4; i++) {
            float mx = fmaxf(fmaxf(s[i][0], s[i][1]), fmaxf(s[i][2], s[i][3]));
            #pragma unroll
            for (int off = 8; off >= 1; off >>= 1)
                mx = fmaxf(mx, __shfl_xor_sync(0xffffffffu, mx, off));
            const float mn = fmaxf(mrow[i], mx);
            const float corr = __expf(mrow[i] - mn);
            mrow[i] = mn;
            float rs = 0.f;
            #pragma unroll
            for (int j = 0; j < 4; j++) {
                s[i][j] = __expf(s[i][j] - mn);
                rs += s[i][j];
            }
            #pragma unroll
            for (int off = 8; off >= 1; off >>= 1)
                rs += __shfl_xor_sync(0xffffffffu, rs, off);
            lrow[i] = lrow[i] * corr + rs;
            #pragma unroll
            for (int j = 0; j < 4; j++) o[i][j] *= corr;
            *(float4*)&Ps[(tr * 4 + i) * 64 + tc * 4] =
                make_float4(s[i][0], s[i][1], s[i][2], s[i][3]);
        }
        __syncthreads();

        {
            const int row = t >> 2;
            const int dg  = (t & 3) * 16;
            const float* src = v + (size_t)(b * TT + jt * 64 + row) * CC + h * HD + dg;
            #pragma unroll
            for (int j = 0; j < 4; j++)
                *(float4*)&KVs[row * 64 + dg + 4 * j] = *(const float4*)(src + 4 * j);
        }
        __syncthreads();

        #pragma unroll 4
        for (int kv = 0; kv < 64; kv += 4) {
            float p[4][4];
            #pragma unroll
            for (int i = 0; i < 4; i++) {
                const float4 pv = *(const float4*)&Ps[(tr * 4 + i) * 64 + kv];
                p[i][0] = pv.x; p[i][1] = pv.y; p[i][2] = pv.z; p[i][3] = pv.w;
            }
            #pragma unroll
            for (int u = 0; u < 4; u++) {
                const float4 vv = *(const float4*)&KVs[(kv + u) * 64 + tc * 4];
                #pragma unroll
                for (int i = 0; i < 4; i++) {
                    o[i][0] += p[i][u] * vv.x;
                    o[i][1] += p[i][u] * vv.y;
                    o[i][2] += p[i][u] * vv.z;
                    o[i][3] += p[i][u] * vv.w;
                }
            }
        }
    }

    #pragma unroll
    for (int i = 0; i < 4; i++) {
        const float inv = 1.0f / lrow[i];
        float* dst = y + (size_t)(b * TT + it * 64 + tr * 4 + i) * CC + h * HD + tc * 4;
        *(float4*)dst = make_float4(o[i][0]*inv, o[i][1]*inv, o[i][2]*inv, o[i][3]*inv);
    }
}

// ---------------- launch ----------------
extern "C" void kernel_launch(void* const* d_in, const int* in_sizes, int n_in,
                              void* d_out, int out_size)
{
    (void)in_sizes; (void)n_in; (void)out_size;
    const float* x     = (const float*)d_in[0];
    const float* ln1_w = (const float*)d_in[1];
    const float* ln1_b = (const float*)d_in[2];
    const float* ln2_w = (const float*)d_in[3];
    const float* ln2_b = (const float*)d_in[4];
    const float* Wq    = (const float*)d_in[5];
    const float* bq    = (const float*)d_in[6];
    const float* Wk    = (const float*)d_in[7];
    const float* bk    = (const float*)d_in[8];
    const float* Wv    = (const float*)d_in[9];
    const float* bv    = (const float*)d_in[10];
    const float* Wp    = (const float*)d_in[11];
    const float* bp    = (const float*)d_in[12];
    const float* W1    = (const float*)d_in[13];
    const float* b1    = (const float*)d_in[14];
    const float* W2    = (const float*)d_in[15];
    const float* b2    = (const float*)d_in[16];
    float* out = (float*)d_out;

    float *h, *q, *k, *v, *x1, *m;
    cudaGetSymbolAddress((void**)&h,  g_h);
    cudaGetSymbolAddress((void**)&q,  g_q);
    cudaGetSymbolAddress((void**)&k,  g_k);
    cudaGetSymbolAddress((void**)&v,  g_v);
    cudaGetSymbolAddress((void**)&x1, g_x1);
    cudaGetSymbolAddress((void**)&m,  g_m);

    // 1) h = LN1(x)
    ln_kernel<<<NROWS, 256>>>(x, ln1_w, ln1_b, h);
    // 2) q,k,v = h @ W{q,k,v}^T + b
    gemm_tf32<0,false><<<dim3(CC/BN, NROWS/BM), 256>>>(h, Wq, bq, nullptr, q, NROWS, CC, CC);
    gemm_tf32<0,false><<<dim3(CC/BN, NROWS/BM), 256>>>(h, Wk, bk, nullptr, k, NROWS, CC, CC);
    gemm_tf32<0,false><<<dim3(CC/BN, NROWS/BM), 256>>>(h, Wv, bv, nullptr, v, NROWS, CC, CC);
    // 3) y = causal-attention(q,k,v)  (into h, free now)
    attn_kernel<<<dim3(BB*HH, TT/64), 256>>>(q, k, v, h);
    // 4) x1 = x + y @ Wp^T + bp
    gemm_tf32<0,true><<<dim3(CC/BN, NROWS/BM), 256>>>(h, Wp, bp, x, x1, NROWS, CC, CC);
    // 5) h2 = LN2(x1)  (into q, free now)
    ln_kernel<<<NROWS, 256>>>(x1, ln2_w, ln2_b, q);
    // 6) m = gelu(h2 @ W1^T + b1)
    gemm_tf32<1,false><<<dim3(FF/BN, NROWS/BM), 256>>>(q, W1, b1, nullptr, m, NROWS, FF, CC);
    // 7) out = x1 + m @ W2^T + b2
    gemm_tf32<0,true><<<dim3(CC/BN, NROWS/BM), 256>>>(m, W2, b2, x1, out, NROWS, CC, FF);
}

// round 5
// speedup vs baseline: 4.7384x; 1.2272x over previous
#include <cuda_runtime.h>
#include <cuda_bf16.h>
#include <math.h>
#include <stdint.h>

// Problem dims (fixed)
#define BB 2
#define TT 2048
#define CC 1024
#define HH 16
#define HD 64
#define NROWS (BB*TT)          // 4096
#define FF (4*CC)              // 4096

// ---------------- scratch (allocation-free rule: __device__ globals) --------
__device__ float g_h [NROWS*CC];
__device__ float g_q [NROWS*CC];
__device__ float g_k [NROWS*CC];
__device__ float g_v [NROWS*CC];
__device__ float g_x1[NROWS*CC];
__device__ float g_m [NROWS*FF];

// ---------------- LayerNorm ----------------
__global__ __launch_bounds__(256)
void ln_kernel(const float* __restrict__ x, const float* __restrict__ w,
               const float* __restrict__ b, float* __restrict__ out)
{
    __shared__ float red[16];
    const int row = blockIdx.x;
    const int t = threadIdx.x;
    const float4* xr = (const float4*)(x + (size_t)row * CC);
    float4 v = xr[t];
    float s  = v.x + v.y + v.z + v.w;
    float ss = v.x*v.x + v.y*v.y + v.z*v.z + v.w*v.w;
    #pragma unroll
    for (int off = 16; off >= 1; off >>= 1) {
        s  += __shfl_xor_sync(0xffffffffu, s,  off);
        ss += __shfl_xor_sync(0xffffffffu, ss, off);
    }
    const int wid = t >> 5, lane = t & 31;
    if (lane == 0) { red[wid] = s; red[8 + wid] = ss; }
    __syncthreads();
    if (t == 0) {
        float S = 0.f, SS = 0.f;
        #pragma unroll
        for (int i = 0; i < 8; i++) { S += red[i]; SS += red[8 + i]; }
        red[0] = S; red[1] = SS;
    }
    __syncthreads();
    const float mu  = red[0] * (1.0f / CC);
    const float var = red[1] * (1.0f / CC) - mu * mu;
    const float rstd = rsqrtf(var + 1e-5f);
    const float4 wv = ((const float4*)w)[t];
    const float4 bv = ((const float4*)b)[t];
    float4 o;
    o.x = (v.x - mu) * rstd * wv.x + bv.x;
    o.y = (v.y - mu) * rstd * wv.y + bv.y;
    o.z = (v.z - mu) * rstd * wv.z + bv.z;
    o.w = (v.w - mu) * rstd * wv.w + bv.w;
    ((float4*)(out + (size_t)row * CC))[t] = o;
}

// ---------------- helpers ----------------
__device__ __forceinline__ float gelu_exact(float v) {
    return 0.5f * v * (1.0f + erff(v * 0.70710678118654752f));
}
__device__ __forceinline__ uint32_t f2tf(float x) {
    uint32_t r; asm("cvt.rna.tf32.f32 %0, %1;" : "=r"(r) : "f"(x)); return r;
}
__device__ __forceinline__ void mma16x8x8(float c[4], const uint32_t a[4], const uint32_t b[2]) {
    asm volatile("mma.sync.aligned.m16n8k8.row.col.f32.tf32.tf32.f32 "
        "{%0,%1,%2,%3}, {%4,%5,%6,%7}, {%8,%9}, {%0,%1,%2,%3};\n"
        : "+f"(c[0]), "+f"(c[1]), "+f"(c[2]), "+f"(c[3])
        : "r"(a[0]), "r"(a[1]), "r"(a[2]), "r"(a[3]), "r"(b[0]), "r"(b[1]));
}
__device__ __forceinline__ void cp16(uint32_t s, const float* g) {
    asm volatile("cp.async.ca.shared.global [%0], [%1], 16;\n" :: "r"(s), "l"(g));
}

// ---------------- tf32 tensor-core GEMM (3-stage pipeline) ------------------
#define BM 128
#define BN 128
#define BK 16
#define LDSK 20
#define GSTG 3
#define GEMM_SMEM (GSTG * 2 * BM * LDSK * 4)   // 61440 bytes

template<int ACT, bool RES>
__global__ __launch_bounds__(256, 2)
void gemm_tf32(const float* __restrict__ A, const float* __restrict__ W,
               const float* __restrict__ bias, const float* __restrict__ res,
               float* __restrict__ out, int M, int N, int K)
{
    extern __shared__ float gsm[];
    float* As = gsm;                         // [GSTG][BM*LDSK]
    float* Bs = gsm + GSTG * BM * LDSK;      // [GSTG][BN*LDSK]

    const int t = threadIdx.x;
    const int wid  = t >> 5;
    const int lane = t & 31;
    const int g    = lane >> 2;
    const int tig  = lane & 3;
    const int wm = (wid & 1) * 64;
    const int wn = (wid >> 1) * 32;
    const int m0 = blockIdx.y * BM;
    const int n0 = blockIdx.x * BN;

    const int lr = t >> 1;
    const int kh = (t & 1) * 8;
    const float* ag = A + (size_t)(m0 + lr) * K + kh;
    const float* bg = W + (size_t)(n0 + lr) * K + kh;
    const uint32_t as_s = (uint32_t)__cvta_generic_to_shared(&As[lr * LDSK + kh]);
    const uint32_t bs_s = (uint32_t)__cvta_generic_to_shared(&Bs[lr * LDSK + kh]);
    const uint32_t stgbytes = BM * LDSK * 4;

    float acc[4][4][4];
    #pragma unroll
    for (int mt = 0; mt < 4; mt++)
        #pragma unroll
        for (int nt = 0; nt < 4; nt++)
            #pragma unroll
            for (int r = 0; r < 4; r++) acc[mt][nt][r] = 0.f;

    const int KT = K / BK;
    // prologue: stage tiles 0,1
    #pragma unroll
    for (int s = 0; s < GSTG - 1; ++s) {
        const uint32_t off = s * stgbytes;
        cp16(as_s + off, ag + s * BK);  cp16(as_s + off + 16, ag + s * BK + 4);
        cp16(bs_s + off, bg + s * BK);  cp16(bs_s + off + 16, bg + s * BK + 4);
        asm volatile("cp.async.commit_group;\n");
    }

    for (int kt = 0; kt < KT; ++kt) {
        asm volatile("cp.async.wait_group %0;\n" :: "n"(GSTG - 2));
        __syncthreads();
        const int pf = kt + GSTG - 1;
        if (pf < KT) {
            const uint32_t off = (pf % GSTG) * stgbytes;
            const float* ag2 = ag + (size_t)pf * BK;
            const float* bg2 = bg + (size_t)pf * BK;
            cp16(as_s + off, ag2);  cp16(as_s + off + 16, ag2 + 4);
            cp16(bs_s + off, bg2);  cp16(bs_s + off + 16, bg2 + 4);
        }
        asm volatile("cp.async.commit_group;\n");

        const float* Ab = As + (kt % GSTG) * BM * LDSK;
        const float* Bb = Bs + (kt % GSTG) * BM * LDSK;
        #pragma unroll
        for (int ks = 0; ks < 2; ++ks) {
            const int k0 = ks * 8;
            uint32_t af[4][4], bf[4][2];
            #pragma unroll
            for (int mt = 0; mt < 4; ++mt) {
                const float* p = Ab + (wm + mt * 16 + g) * LDSK + k0 + tig;
                af[mt][0] = f2tf(p[0]);
                af[mt][1] = f2tf(p[8 * LDSK]);
                af[mt][2] = f2tf(p[4]);
                af[mt][3] = f2tf(p[8 * LDSK + 4]);
            }
            #pragma unroll
            for (int nt = 0; nt < 4; ++nt) {
                const float* p = Bb + (wn + nt * 8 + g) * LDSK + k0 + tig;
                bf[nt][0] = f2tf(p[0]);
                bf[nt][1] = f2tf(p[4]);
            }
            #pragma unroll
            for (int mt = 0; mt < 4; ++mt)
                #pragma unroll
                for (int nt = 0; nt < 4; ++nt)
                    mma16x8x8(acc[mt][nt], af[mt], bf[nt]);
        }
    }

    #pragma unroll
    for (int nt = 0; nt < 4; ++nt) {
        const int col = n0 + wn + nt * 8 + 2 * tig;
        const float2 bc = *(const float2*)(bias + col);
        #pragma unroll
        for (int mt = 0; mt < 4; ++mt) {
            const int row = m0 + wm + mt * 16 + g;
            float v0 = acc[mt][nt][0] + bc.x;
            float v1 = acc[mt][nt][1] + bc.y;
            float v2 = acc[mt][nt][2] + bc.x;
            float v3 = acc[mt][nt][3] + bc.y;
            if (ACT == 1) {
                v0 = gelu_exact(v0); v1 = gelu_exact(v1);
                v2 = gelu_exact(v2); v3 = gelu_exact(v3);
            }
            if (RES) {
                const float2 r0 = *(const float2*)(res + (size_t)row * N + col);
                const float2 r1 = *(const float2*)(res + (size_t)(row + 8) * N + col);
                v0 += r0.x; v1 += r0.y; v2 += r1.x; v3 += r1.y;
            }
            *(float2*)(out + (size_t)row * N + col)       = make_float2(v0, v1);
            *(float2*)(out + (size_t)(row + 8) * N + col) = make_float2(v2, v3);
        }
    }
}

// ---------------- Flash attention, tf32 tensor cores ------------------------
// BQ=128 (8 warps x m16), BKV=64, HD=64. Padded smem stride 68 (conflict-free).
#define ATS 68
#define ATTN_SMEM ((128*ATS + 64*ATS + 128*ATS) * 4)   // 87040 bytes

__global__ __launch_bounds__(256, 2)
void attn_mma(const float* __restrict__ q, const float* __restrict__ k,
              const float* __restrict__ v, float* __restrict__ y)
{
    extern __shared__ uint32_t smu[];
    uint32_t* Qs  = smu;                       // [128][ATS] tf32
    uint32_t* KVs = smu + 128 * ATS;           // [64][ATS]  tf32 (K then V)
    uint32_t* Ps  = smu + (128 + 64) * ATS;    // [128][ATS] tf32

    const int bh = blockIdx.x;
    const int b  = bh >> 4;
    const int h  = bh & 15;
    const int it = (int)gridDim.y - 1 - blockIdx.y;  // heavy tiles first
    const int t  = threadIdx.x;
    const int wid  = t >> 5;
    const int lane = t & 31;
    const int g    = lane >> 2;
    const int tig  = lane & 3;
    const int wm = wid * 16;

    // load Q tile [128][64], scale, convert to tf32
    #pragma unroll
    for (int j = 0; j < 8; ++j) {
        const int fid = t + j * 256;
        const int row = fid >> 4;
        const int d4  = (fid & 15) * 4;
        const float4 vv = *(const float4*)(q + (size_t)(b * TT + it * 128 + row) * CC + h * HD + d4);
        uint4 u;
        u.x = f2tf(vv.x * 0.125f); u.y = f2tf(vv.y * 0.125f);
        u.z = f2tf(vv.z * 0.125f); u.w = f2tf(vv.w * 0.125f);
        *(uint4*)&Qs[row * ATS + d4] = u;
    }

    float oc[8][4];
    #pragma unroll
    for (int nt = 0; nt < 8; ++nt)
        #pragma unroll
        for (int r = 0; r < 4; ++r) oc[nt][r] = 0.f;
    float m0 = -INFINITY, m1 = -INFINITY, l0 = 0.f, l1 = 0.f;

    const int JT = 2 * it + 2;
    for (int jt = 0; jt < JT; ++jt) {
        __syncthreads();   // KV/P buffers free
        // load K tile [64][64] -> KVs
        #pragma unroll
        for (int j = 0; j < 4; ++j) {
            const int fid = t + j * 256;
            const int row = fid >> 4;
            const int d4  = (fid & 15) * 4;
            const float4 vv = *(const float4*)(k + (size_t)(b * TT + jt * 64 + row) * CC + h * HD + d4);
            uint4 u; u.x = f2tf(vv.x); u.y = f2tf(vv.y); u.z = f2tf(vv.z); u.w = f2tf(vv.w);
            *(uint4*)&KVs[row * ATS + d4] = u;
        }
        __syncthreads();

        // S = Q @ K^T for this warp's 16 rows
        float sc[8][4];
        #pragma unroll
        for (int nt = 0; nt < 8; ++nt)
            #pragma unroll
            for (int r = 0; r < 4; ++r) sc[nt][r] = 0.f;
        #pragma unroll
        for (int ks = 0; ks < 8; ++ks) {
            const int base = (wm + g) * ATS + ks * 8 + tig;
            uint32_t a[4];
            a[0] = Qs[base];            a[1] = Qs[base + 8 * ATS];
            a[2] = Qs[base + 4];        a[3] = Qs[base + 8 * ATS + 4];
            #pragma unroll
            for (int nt = 0; nt < 8; ++nt) {
                uint32_t bb[2];
                bb[0] = KVs[(nt * 8 + g) * ATS + ks * 8 + tig];
                bb[1] = KVs[(nt * 8 + g) * ATS + ks * 8 + tig + 4];
                mma16x8x8(sc[nt], a, bb);
            }
        }

        // causal mask (only the two diagonal kv tiles need it)
        if (jt >= 2 * it) {
            const int r0 = it * 128 + wm + g;
            const int r1 = r0 + 8;
            const int cb = jt * 64 + 2 * tig;
            #pragma unroll
            for (int nt = 0; nt < 8; ++nt) {
                const int c0 = cb + nt * 8;
                if (c0     > r0) sc[nt][0] = -1e30f;
                if (c0 + 1 > r0) sc[nt][1] = -1e30f;
                if (c0     > r1) sc[nt][2] = -1e30f;
                if (c0 + 1 > r1) sc[nt][3] = -1e30f;
            }
        }

        // online softmax (rows g and g+8; cols spread across quad lanes)
        float mx0 = -INFINITY, mx1 = -INFINITY;
        #pragma unroll
        for (int nt = 0; nt < 8; ++nt) {
            mx0 = fmaxf(mx0, fmaxf(sc[nt][0], sc[nt][1]));
            mx1 = fmaxf(mx1, fmaxf(sc[nt][2], sc[nt][3]));
        }
        mx0 = fmaxf(mx0, __shfl_xor_sync(0xffffffffu, mx0, 1));
        mx0 = fmaxf(mx0, __shfl_xor_sync(0xffffffffu, mx0, 2));
        mx1 = fmaxf(mx1, __shfl_xor_sync(0xffffffffu, mx1, 1));
        mx1 = fmaxf(mx1, __shfl_xor_sync(0xffffffffu, mx1, 2));
        const float mn0 = fmaxf(m0, mx0), mn1 = fmaxf(m1, mx1);
        const float cr0 = __expf(m0 - mn0), cr1 = __expf(m1 - mn1);
        m0 = mn0; m1 = mn1;
        float s0 = 0.f, s1 = 0.f;
        #pragma unroll
        for (int nt = 0; nt < 8; ++nt) {
            sc[nt][0] = __expf(sc[nt][0] - mn0);
            sc[nt][1] = __expf(sc[nt][1] - mn0);
            sc[nt][2] = __expf(sc[nt][2] - mn1);
            sc[nt][3] = __expf(sc[nt][3] - mn1);
            s0 += sc[nt][0] + sc[nt][1];
            s1 += sc[nt][2] + sc[nt][3];
            uint2 p01; p01.x = f2tf(sc[nt][0]); p01.y = f2tf(sc[nt][1]);
            uint2 p23; p23.x = f2tf(sc[nt][2]); p23.y = f2tf(sc[nt][3]);
            *(uint2*)&Ps[(wm + g) * ATS + nt * 8 + 2 * tig]     = p01;
            *(uint2*)&Ps[(wm + g + 8) * ATS + nt * 8 + 2 * tig] = p23;
        }
        s0 += __shfl_xor_sync(0xffffffffu, s0, 1);
        s0 += __shfl_xor_sync(0xffffffffu, s0, 2);
        s1 += __shfl_xor_sync(0xffffffffu, s1, 1);
        s1 += __shfl_xor_sync(0xffffffffu, s1, 2);
        l0 = l0 * cr0 + s0;
        l1 = l1 * cr1 + s1;
        #pragma unroll
        for (int nt = 0; nt < 8; ++nt) {
            oc[nt][0] *= cr0; oc[nt][1] *= cr0;
            oc[nt][2] *= cr1; oc[nt][3] *= cr1;
        }
        __syncthreads();   // all warps done reading K from KVs

        // load V tile [64][64] -> KVs
        #pragma unroll
        for (int j = 0; j < 4; ++j) {
            const int fid = t + j * 256;
            const int row = fid >> 4;
            const int d4  = (fid & 15) * 4;
            const float4 vv = *(const float4*)(v + (size_t)(b * TT + jt * 64 + row) * CC + h * HD + d4);
            uint4 u; u.x = f2tf(vv.x); u.y = f2tf(vv.y); u.z = f2tf(vv.z); u.w = f2tf(vv.w);
            *(uint4*)&KVs[row * ATS + d4] = u;
        }
        __syncthreads();

        // O += P @ V
        #pragma unroll
        for (int ks = 0; ks < 8; ++ks) {
            const int base = (wm + g) * ATS + ks * 8 + tig;
            uint32_t a[4];
            a[0] = Ps[base];            a[1] = Ps[base + 8 * ATS];
            a[2] = Ps[base + 4];        a[3] = Ps[base + 8 * ATS + 4];
            #pragma unroll
            for (int nt = 0; nt < 8; ++nt) {
                uint32_t bb[2];
                bb[0] = KVs[(ks * 8 + tig) * ATS + nt * 8 + g];
                bb[1] = KVs[(ks * 8 + tig + 4) * ATS + nt * 8 + g];
                mma16x8x8(oc[nt], a, bb);
            }
        }
    }

    // finalize + store
    const float inv0 = 1.0f / l0, inv1 = 1.0f / l1;
    const size_t r0 = (size_t)(b * TT + it * 128 + wm + g);
    #pragma unroll
    for (int nt = 0; nt < 8; ++nt) {
        const int col = h * HD + nt * 8 + 2 * tig;
        *(float2*)(y + r0 * CC + col)       = make_float2(oc[nt][0] * inv0, oc[nt][1] * inv0);
        *(float2*)(y + (r0 + 8) * CC + col) = make_float2(oc[nt][2] * inv1, oc[nt][3] * inv1);
    }
}

// ---------------- launch ----------------
extern "C" void kernel_launch(void* const* d_in, const int* in_sizes, int n_in,
                              void* d_out, int out_size)
{
    (void)in_sizes; (void)n_in; (void)out_size;
    const float* x     = (const float*)d_in[0];
    const float* ln1_w = (const float*)d_in[1];
    const float* ln1_b = (const float*)d_in[2];
    const float* ln2_w = (const float*)d_in[3];
    const float* ln2_b = (const float*)d_in[4];
    const float* Wq    = (const float*)d_in[5];
    const float* bq    = (const float*)d_in[6];
    const float* Wk    = (const float*)d_in[7];
    const float* bk    = (const float*)d_in[8];
    const float* Wv    = (const float*)d_in[9];
    const float* bv    = (const float*)d_in[10];
    const float* Wp    = (const float*)d_in[11];
    const float* bp    = (const float*)d_in[12];
    const float* W1    = (const float*)d_in[13];
    const float* b1    = (const float*)d_in[14];
    const float* W2    = (const float*)d_in[15];
    const float* b2    = (const float*)d_in[16];
    float* out = (float*)d_out;

    float *h, *q, *k, *v, *x1, *m;
    cudaGetSymbolAddress((void**)&h,  g_h);
    cudaGetSymbolAddress((void**)&q,  g_q);
    cudaGetSymbolAddress((void**)&k,  g_k);
    cudaGetSymbolAddress((void**)&v,  g_v);
    cudaGetSymbolAddress((void**)&x1, g_x1);
    cudaGetSymbolAddress((void**)&m,  g_m);

    cudaFuncSetAttribute(gemm_tf32<0,false>, cudaFuncAttributeMaxDynamicSharedMemorySize, GEMM_SMEM);
    cudaFuncSetAttribute(gemm_tf32<0,true >, cudaFuncAttributeMaxDynamicSharedMemorySize, GEMM_SMEM);
    cudaFuncSetAttribute(gemm_tf32<1,false>, cudaFuncAttributeMaxDynamicSharedMemorySize, GEMM_SMEM);
    cudaFuncSetAttribute(attn_mma, cudaFuncAttributeMaxDynamicSharedMemorySize, ATTN_SMEM);

    // 1) h = LN1(x)
    ln_kernel<<<NROWS, 256>>>(x, ln1_w, ln1_b, h);
    // 2) q,k,v = h @ W{q,k,v}^T + b
    gemm_tf32<0,false><<<dim3(CC/BN, NROWS/BM), 256, GEMM_SMEM>>>(h, Wq, bq, nullptr, q, NROWS, CC, CC);
    gemm_tf32<0,false><<<dim3(CC/BN, NROWS/BM), 256, GEMM_SMEM>>>(h, Wk, bk, nullptr, k, NROWS, CC, CC);
    gemm_tf32<0,false><<<dim3(CC/BN, NROWS/BM), 256, GEMM_SMEM>>>(h, Wv, bv, nullptr, v, NROWS, CC, CC);
    // 3) y = causal-attention(q,k,v)  (into h, free now)
    attn_mma<<<dim3(BB*HH, TT/128), 256, ATTN_SMEM>>>(q, k, v, h);
    // 4) x1 = x + y @ Wp^T + bp
    gemm_tf32<0,true><<<dim3(CC/BN, NROWS/BM), 256, GEMM_SMEM>>>(h, Wp, bp, x, x1, NROWS, CC, CC);
    // 5) h2 = LN2(x1)  (into q, free now)
    ln_kernel<<<NROWS, 256>>>(x1, ln2_w, ln2_b, q);
    // 6) m = gelu(h2 @ W1^T + b1)
    gemm_tf32<1,false><<<dim3(FF/BN, NROWS/BM), 256, GEMM_SMEM>>>(q, W1, b1, nullptr, m, NROWS, FF, CC);
    // 7) out = x1 + m @ W2^T + b2
    gemm_tf32<0,true><<<dim3(CC/BN, NROWS/BM), 256, GEMM_SMEM>>>(m, W2, b2, x1, out, NROWS, CC, FF);
}

// round 6
// speedup vs baseline: 4.8213x; 1.0175x over previous
#include <cuda_runtime.h>
#include <cuda_bf16.h>
#include <math.h>
#include <stdint.h>

// Problem dims (fixed)
#define BB 2
#define TT 2048
#define CC 1024
#define HH 16
#define HD 64
#define NROWS (BB*TT)          // 4096
#define FF (4*CC)              // 4096
#define QST 3072               // fused qkv row stride

// ---------------- scratch (__device__ globals; no allocs allowed) -----------
__device__ float g_h   [NROWS*CC];    // LN1 out (biased bits); later attn y
__device__ float g_qkv [NROWS*QST];   // fused qkv (biased); later h2 (first 4M)
__device__ float g_x1  [NROWS*CC];    // x after attention residual (plain)
__device__ float g_m   [NROWS*FF];    // MLP hidden (biased)
__device__ float g_wqkv[QST*CC];      // rounded Wq|Wk|Wv
__device__ float g_wp  [CC*CC];       // rounded Wp
__device__ float g_w1  [FF*CC];       // rounded W1
__device__ float g_w2  [CC*FF];       // rounded W2
__device__ float g_bqkv[QST];         // bq|bk|bv (plain)

// RNA-to-tf32 equivalent: add half-ulp to fp32 bits; HMMA truncates low 13.
__device__ __forceinline__ float biasbits(float v) {
    return __uint_as_float(__float_as_uint(v) + 0x1000u);
}

// ---------------- setup: rounded weight copies / bias concat ----------------
__global__ __launch_bounds__(256)
void round_copy(const uint4* __restrict__ src, uint4* __restrict__ dst, int n4)
{
    int i = blockIdx.x * 256 + threadIdx.x;
    if (i < n4) {
        uint4 u = src[i];
        u.x += 0x1000u; u.y += 0x1000u; u.z += 0x1000u; u.w += 0x1000u;
        dst[i] = u;
    }
}
__global__ __launch_bounds__(1024)
void bias_concat(const float* __restrict__ bq, const float* __restrict__ bk,
                 const float* __restrict__ bv, float* __restrict__ dst)
{
    int i = blockIdx.x * 1024 + threadIdx.x;
    dst[i]        = bq[i];
    dst[i + 1024] = bk[i];
    dst[i + 2048] = bv[i];
}

// ---------------- LayerNorm (writes biased bits) ----------------
__global__ __launch_bounds__(256)
void ln_kernel(const float* __restrict__ x, const float* __restrict__ w,
               const float* __restrict__ b, float* __restrict__ out)
{
    __shared__ float red[16];
    const int row = blockIdx.x;
    const int t = threadIdx.x;
    const float4* xr = (const float4*)(x + (size_t)row * CC);
    float4 v = xr[t];
    float s  = v.x + v.y + v.z + v.w;
    float ss = v.x*v.x + v.y*v.y + v.z*v.z + v.w*v.w;
    #pragma unroll
    for (int off = 16; off >= 1; off >>= 1) {
        s  += __shfl_xor_sync(0xffffffffu, s,  off);
        ss += __shfl_xor_sync(0xffffffffu, ss, off);
    }
    const int wid = t >> 5, lane = t & 31;
    if (lane == 0) { red[wid] = s; red[8 + wid] = ss; }
    __syncthreads();
    if (t == 0) {
        float S = 0.f, SS = 0.f;
        #pragma unroll
        for (int i = 0; i < 8; i++) { S += red[i]; SS += red[8 + i]; }
        red[0] = S; red[1] = SS;
    }
    __syncthreads();
    const float mu  = red[0] * (1.0f / CC);
    const float var = red[1] * (1.0f / CC) - mu * mu;
    const float rstd = rsqrtf(var + 1e-5f);
    const float4 wv = ((const float4*)w)[t];
    const float4 bv = ((const float4*)b)[t];
    float4 o;
    o.x = biasbits((v.x - mu) * rstd * wv.x + bv.x);
    o.y = biasbits((v.y - mu) * rstd * wv.y + bv.y);
    o.z = biasbits((v.z - mu) * rstd * wv.z + bv.z);
    o.w = biasbits((v.w - mu) * rstd * wv.w + bv.w);
    ((float4*)(out + (size_t)row * CC))[t] = o;
}

// ---------------- helpers ----------------
__device__ __forceinline__ float gelu_exact(float v) {
    return 0.5f * v * (1.0f + erff(v * 0.70710678118654752f));
}
__device__ __forceinline__ uint32_t f2tf(float x) {
    uint32_t r; asm("cvt.rna.tf32.f32 %0, %1;" : "=r"(r) : "f"(x)); return r;
}
__device__ __forceinline__ void mma16x8x8(float c[4], const uint32_t a[4], const uint32_t b[2]) {
    asm volatile("mma.sync.aligned.m16n8k8.row.col.f32.tf32.tf32.f32 "
        "{%0,%1,%2,%3}, {%4,%5,%6,%7}, {%8,%9}, {%0,%1,%2,%3};\n"
        : "+f"(c[0]), "+f"(c[1]), "+f"(c[2]), "+f"(c[3])
        : "r"(a[0]), "r"(a[1]), "r"(a[2]), "r"(a[3]), "r"(b[0]), "r"(b[1]));
}
__device__ __forceinline__ void cp16(uint32_t s, const float* g) {
    asm volatile("cp.async.ca.shared.global [%0], [%1], 16;\n" :: "r"(s), "l"(g));
}

// ---------------- tf32 tensor-core GEMM (2-stage, no inner-loop cvt) --------
#define BM 128
#define BN 128
#define BK 16
#define LDSK 20
#define GEMM_SMEM (2 * 2 * BM * LDSK * 4)   // 40960 bytes

template<int ACT, bool RES, bool ROUND>
__global__ __launch_bounds__(256, 2)
void gemm_tf32(const float* __restrict__ A, const float* __restrict__ W,
               const float* __restrict__ bias, const float* __restrict__ res,
               float* __restrict__ out, int M, int N, int K)
{
    extern __shared__ float gsm[];
    float* As = gsm;                    // [2][BM*LDSK]
    float* Bs = gsm + 2 * BM * LDSK;    // [2][BN*LDSK]

    const int t = threadIdx.x;
    const int wid  = t >> 5;
    const int lane = t & 31;
    const int g    = lane >> 2;
    const int tig  = lane & 3;
    const int wm = (wid & 1) * 64;
    const int wn = (wid >> 1) * 32;
    const int m0 = blockIdx.y * BM;
    const int n0 = blockIdx.x * BN;

    const int lr = t >> 1;
    const int kh = (t & 1) * 8;
    const float* ag = A + (size_t)(m0 + lr) * K + kh;
    const float* bg = W + (size_t)(n0 + lr) * K + kh;
    const uint32_t as_s = (uint32_t)__cvta_generic_to_shared(&As[lr * LDSK + kh]);
    const uint32_t bs_s = (uint32_t)__cvta_generic_to_shared(&Bs[lr * LDSK + kh]);
    const uint32_t stgbytes = BM * LDSK * 4;

    float acc[4][4][4];
    #pragma unroll
    for (int mt = 0; mt < 4; mt++)
        #pragma unroll
        for (int nt = 0; nt < 4; nt++)
            #pragma unroll
            for (int r = 0; r < 4; r++) acc[mt][nt][r] = 0.f;

    const int KT = K / BK;
    cp16(as_s, ag);      cp16(as_s + 16, ag + 4);
    cp16(bs_s, bg);      cp16(bs_s + 16, bg + 4);
    asm volatile("cp.async.commit_group;\n");

    for (int kt = 0; kt < KT; ++kt) {
        if (kt + 1 < KT) {
            const float* ag2 = ag + (size_t)(kt + 1) * BK;
            const float* bg2 = bg + (size_t)(kt + 1) * BK;
            const uint32_t off = ((kt + 1) & 1) * stgbytes;
            cp16(as_s + off, ag2);  cp16(as_s + off + 16, ag2 + 4);
            cp16(bs_s + off, bg2);  cp16(bs_s + off + 16, bg2 + 4);
            asm volatile("cp.async.commit_group;\n");
            asm volatile("cp.async.wait_group 1;\n");
        } else {
            asm volatile("cp.async.wait_group 0;\n");
        }
        __syncthreads();
        const uint32_t* Ab = (const uint32_t*)(As + (kt & 1) * BM * LDSK);
        const uint32_t* Bb = (const uint32_t*)(Bs + (kt & 1) * BM * LDSK);
        #pragma unroll
        for (int ks = 0; ks < 2; ++ks) {
            const int k0 = ks * 8;
            uint32_t af[4][4], bf[4][2];
            #pragma unroll
            for (int mt = 0; mt < 4; ++mt) {
                const uint32_t* p = Ab + (wm + mt * 16 + g) * LDSK + k0 + tig;
                af[mt][0] = p[0];
                af[mt][1] = p[8 * LDSK];
                af[mt][2] = p[4];
                af[mt][3] = p[8 * LDSK + 4];
            }
            #pragma unroll
            for (int nt = 0; nt < 4; ++nt) {
                const uint32_t* p = Bb + (wn + nt * 8 + g) * LDSK + k0 + tig;
                bf[nt][0] = p[0];
                bf[nt][1] = p[4];
            }
            #pragma unroll
            for (int mt = 0; mt < 4; ++mt)
                #pragma unroll
                for (int nt = 0; nt < 4; ++nt)
                    mma16x8x8(acc[mt][nt], af[mt], bf[nt]);
        }
        __syncthreads();
    }

    #pragma unroll
    for (int nt = 0; nt < 4; ++nt) {
        const int col = n0 + wn + nt * 8 + 2 * tig;
        const float2 bc = *(const float2*)(bias + col);
        #pragma unroll
        for (int mt = 0; mt < 4; ++mt) {
            const int row = m0 + wm + mt * 16 + g;
            float v0 = acc[mt][nt][0] + bc.x;
            float v1 = acc[mt][nt][1] + bc.y;
            float v2 = acc[mt][nt][2] + bc.x;
            float v3 = acc[mt][nt][3] + bc.y;
            if (ACT == 1) {
                v0 = gelu_exact(v0); v1 = gelu_exact(v1);
                v2 = gelu_exact(v2); v3 = gelu_exact(v3);
            }
            if (RES) {
                const float2 r0 = *(const float2*)(res + (size_t)row * N + col);
                const float2 r1 = *(const float2*)(res + (size_t)(row + 8) * N + col);
                v0 += r0.x; v1 += r0.y; v2 += r1.x; v3 += r1.y;
            }
            if (ROUND) {
                v0 = biasbits(v0); v1 = biasbits(v1);
                v2 = biasbits(v2); v3 = biasbits(v3);
            }
            *(float2*)(out + (size_t)row * N + col)       = make_float2(v0, v1);
            *(float2*)(out + (size_t)(row + 8) * N + col) = make_float2(v2, v3);
        }
    }
}

// ---------------- Flash attention, tf32 tensor cores ------------------------
// BQ=128 (8 warps x m16), BKV=64, HD=64. qkv is fused [rows][3072], pre-biased.
#define ATS 68
#define ATTN_SMEM ((128*ATS + 64*ATS + 128*ATS) * 4)   // 87040 bytes

__global__ __launch_bounds__(256, 2)
void attn_mma(const float* __restrict__ qkv, float* __restrict__ y)
{
    extern __shared__ uint32_t smu[];
    uint32_t* Qs  = smu;                       // [128][ATS] tf32
    uint32_t* KVs = smu + 128 * ATS;           // [64][ATS]  (K then V)
    uint32_t* Ps  = smu + (128 + 64) * ATS;    // [128][ATS]

    const int bh = blockIdx.x;
    const int b  = bh >> 4;
    const int h  = bh & 15;
    const int it = (int)gridDim.y - 1 - blockIdx.y;  // heavy tiles first
    const int t  = threadIdx.x;
    const int wid  = t >> 5;
    const int lane = t & 31;
    const int g    = lane >> 2;
    const int tig  = lane & 3;
    const int wm = wid * 16;

    // load Q tile [128][64], scale, convert (RNA) to tf32
    #pragma unroll
    for (int j = 0; j < 8; ++j) {
        const int fid = t + j * 256;
        const int row = fid >> 4;
        const int d4  = (fid & 15) * 4;
        const float4 vv = *(const float4*)(qkv + (size_t)(b * TT + it * 128 + row) * QST + h * HD + d4);
        uint4 u;
        u.x = f2tf(vv.x * 0.125f); u.y = f2tf(vv.y * 0.125f);
        u.z = f2tf(vv.z * 0.125f); u.w = f2tf(vv.w * 0.125f);
        *(uint4*)&Qs[row * ATS + d4] = u;
    }

    float oc[8][4];
    #pragma unroll
    for (int nt = 0; nt < 8; ++nt)
        #pragma unroll
        for (int r = 0; r < 4; ++r) oc[nt][r] = 0.f;
    float m0 = -INFINITY, m1 = -INFINITY, l0 = 0.f, l1 = 0.f;

    const int JT = 2 * it + 2;
    for (int jt = 0; jt < JT; ++jt) {
        __syncthreads();
        // K tile (pre-biased bits -> raw copy)
        #pragma unroll
        for (int j = 0; j < 4; ++j) {
            const int fid = t + j * 256;
            const int row = fid >> 4;
            const int d4  = (fid & 15) * 4;
            *(uint4*)&KVs[row * ATS + d4] =
                *(const uint4*)(qkv + (size_t)(b * TT + jt * 64 + row) * QST + CC + h * HD + d4);
        }
        __syncthreads();

        float sc[8][4];
        #pragma unroll
        for (int nt = 0; nt < 8; ++nt)
            #pragma unroll
            for (int r = 0; r < 4; ++r) sc[nt][r] = 0.f;
        #pragma unroll
        for (int ks = 0; ks < 8; ++ks) {
            const int base = (wm + g) * ATS + ks * 8 + tig;
            uint32_t a[4];
            a[0] = Qs[base];            a[1] = Qs[base + 8 * ATS];
            a[2] = Qs[base + 4];        a[3] = Qs[base + 8 * ATS + 4];
            #pragma unroll
            for (int nt = 0; nt < 8; ++nt) {
                uint32_t bb[2];
                bb[0] = KVs[(nt * 8 + g) * ATS + ks * 8 + tig];
                bb[1] = KVs[(nt * 8 + g) * ATS + ks * 8 + tig + 4];
                mma16x8x8(sc[nt], a, bb);
            }
        }

        if (jt >= 2 * it) {
            const int r0 = it * 128 + wm + g;
            const int r1 = r0 + 8;
            const int cb = jt * 64 + 2 * tig;
            #pragma unroll
            for (int nt = 0; nt < 8; ++nt) {
                const int c0 = cb + nt * 8;
                if (c0     > r0) sc[nt][0] = -1e30f;
                if (c0 + 1 > r0) sc[nt][1] = -1e30f;
                if (c0     > r1) sc[nt][2] = -1e30f;
                if (c0 + 1 > r1) sc[nt][3] = -1e30f;
            }
        }

        float mx0 = -INFINITY, mx1 = -INFINITY;
        #pragma unroll
        for (int nt = 0; nt < 8; ++nt) {
            mx0 = fmaxf(mx0, fmaxf(sc[nt][0], sc[nt][1]));
            mx1 = fmaxf(mx1, fmaxf(sc[nt][2], sc[nt][3]));
        }
        mx0 = fmaxf(mx0, __shfl_xor_sync(0xffffffffu, mx0, 1));
        mx0 = fmaxf(mx0, __shfl_xor_sync(0xffffffffu, mx0, 2));
        mx1 = fmaxf(mx1, __shfl_xor_sync(0xffffffffu, mx1, 1));
        mx1 = fmaxf(mx1, __shfl_xor_sync(0xffffffffu, mx1, 2));
        const float mn0 = fmaxf(m0, mx0), mn1 = fmaxf(m1, mx1);
        const float cr0 = __expf(m0 - mn0), cr1 = __expf(m1 - mn1);
        m0 = mn0; m1 = mn1;
        float s0 = 0.f, s1 = 0.f;
        #pragma unroll
        for (int nt = 0; nt < 8; ++nt) {
            sc[nt][0] = __expf(sc[nt][0] - mn0);
            sc[nt][1] = __expf(sc[nt][1] - mn0);
            sc[nt][2] = __expf(sc[nt][2] - mn1);
            sc[nt][3] = __expf(sc[nt][3] - mn1);
            s0 += sc[nt][0] + sc[nt][1];
            s1 += sc[nt][2] + sc[nt][3];
            uint2 p01, p23;   // RNA via +half-ulp; HMMA truncates
            p01.x = __float_as_uint(sc[nt][0]) + 0x1000u;
            p01.y = __float_as_uint(sc[nt][1]) + 0x1000u;
            p23.x = __float_as_uint(sc[nt][2]) + 0x1000u;
            p23.y = __float_as_uint(sc[nt][3]) + 0x1000u;
            *(uint2*)&Ps[(wm + g) * ATS + nt * 8 + 2 * tig]     = p01;
            *(uint2*)&Ps[(wm + g + 8) * ATS + nt * 8 + 2 * tig] = p23;
        }
        s0 += __shfl_xor_sync(0xffffffffu, s0, 1);
        s0 += __shfl_xor_sync(0xffffffffu, s0, 2);
        s1 += __shfl_xor_sync(0xffffffffu, s1, 1);
        s1 += __shfl_xor_sync(0xffffffffu, s1, 2);
        l0 = l0 * cr0 + s0;
        l1 = l1 * cr1 + s1;
        #pragma unroll
        for (int nt = 0; nt < 8; ++nt) {
            oc[nt][0] *= cr0; oc[nt][1] *= cr0;
            oc[nt][2] *= cr1; oc[nt][3] *= cr1;
        }
        __syncthreads();

        // V tile (pre-biased bits -> raw copy)
        #pragma unroll
        for (int j = 0; j < 4; ++j) {
            const int fid = t + j * 256;
            const int row = fid >> 4;
            const int d4  = (fid & 15) * 4;
            *(uint4*)&KVs[row * ATS + d4] =
                *(const uint4*)(qkv + (size_t)(b * TT + jt * 64 + row) * QST + 2 * CC + h * HD + d4);
        }
        __syncthreads();

        #pragma unroll
        for (int ks = 0; ks < 8; ++ks) {
            const int base = (wm + g) * ATS + ks * 8 + tig;
            uint32_t a[4];
            a[0] = Ps[base];            a[1] = Ps[base + 8 * ATS];
            a[2] = Ps[base + 4];        a[3] = Ps[base + 8 * ATS + 4];
            #pragma unroll
            for (int nt = 0; nt < 8; ++nt) {
                uint32_t bb[2];
                bb[0] = KVs[(ks * 8 + tig) * ATS + nt * 8 + g];
                bb[1] = KVs[(ks * 8 + tig + 4) * ATS + nt * 8 + g];
                mma16x8x8(oc[nt], a, bb);
            }
        }
    }

    // finalize + store (biased bits: y feeds the proj GEMM only)
    const float inv0 = 1.0f / l0, inv1 = 1.0f / l1;
    const size_t r0 = (size_t)(b * TT + it * 128 + wm + g);
    #pragma unroll
    for (int nt = 0; nt < 8; ++nt) {
        const int col = h * HD + nt * 8 + 2 * tig;
        *(float2*)(y + r0 * CC + col) =
            make_float2(biasbits(oc[nt][0] * inv0), biasbits(oc[nt][1] * inv0));
        *(float2*)(y + (r0 + 8) * CC + col) =
            make_float2(biasbits(oc[nt][2] * inv1), biasbits(oc[nt][3] * inv1));
    }
}

// ---------------- launch ----------------
extern "C" void kernel_launch(void* const* d_in, const int* in_sizes, int n_in,
                              void* d_out, int out_size)
{
    (void)in_sizes; (void)n_in; (void)out_size;
    const float* x     = (const float*)d_in[0];
    const float* ln1_w = (const float*)d_in[1];
    const float* ln1_b = (const float*)d_in[2];
    const float* ln2_w = (const float*)d_in[3];
    const float* ln2_b = (const float*)d_in[4];
    const float* Wq    = (const float*)d_in[5];
    const float* bq    = (const float*)d_in[6];
    const float* Wk    = (const float*)d_in[7];
    const float* bk    = (const float*)d_in[8];
    const float* Wv    = (const float*)d_in[9];
    const float* bv    = (const float*)d_in[10];
    const float* Wp    = (const float*)d_in[11];
    const float* bp    = (const float*)d_in[12];
    const float* W1    = (const float*)d_in[13];
    const float* b1    = (const float*)d_in[14];
    const float* W2    = (const float*)d_in[15];
    const float* b2    = (const float*)d_in[16];
    float* out = (float*)d_out;

    float *h, *qkv, *x1, *m, *wqkv, *wp, *w1, *w2, *bqkv;
    cudaGetSymbolAddress((void**)&h,    g_h);
    cudaGetSymbolAddress((void**)&qkv,  g_qkv);
    cudaGetSymbolAddress((void**)&x1,   g_x1);
    cudaGetSymbolAddress((void**)&m,    g_m);
    cudaGetSymbolAddress((void**)&wqkv, g_wqkv);
    cudaGetSymbolAddress((void**)&wp,   g_wp);
    cudaGetSymbolAddress((void**)&w1,   g_w1);
    cudaGetSymbolAddress((void**)&w2,   g_w2);
    cudaGetSymbolAddress((void**)&bqkv, g_bqkv);
    float* h2 = qkv;   // reuse: qkv dead after attention

    cudaFuncSetAttribute(gemm_tf32<0,false,true >, cudaFuncAttributeMaxDynamicSharedMemorySize, GEMM_SMEM);
    cudaFuncSetAttribute(gemm_tf32<0,true ,false>, cudaFuncAttributeMaxDynamicSharedMemorySize, GEMM_SMEM);
    cudaFuncSetAttribute(gemm_tf32<1,false,true >, cudaFuncAttributeMaxDynamicSharedMemorySize, GEMM_SMEM);
    cudaFuncSetAttribute(attn_mma, cudaFuncAttributeMaxDynamicSharedMemorySize, ATTN_SMEM);

    // 0) setup: rounded weights + fused qkv bias
    const int W1M4 = CC*CC/4, W4M4 = FF*CC/4;
    round_copy<<<W1M4/256, 256>>>((const uint4*)Wq, (uint4*)wqkv,               W1M4);
    round_copy<<<W1M4/256, 256>>>((const uint4*)Wk, (uint4*)(wqkv + CC*CC),     W1M4);
    round_copy<<<W1M4/256, 256>>>((const uint4*)Wv, (uint4*)(wqkv + 2*CC*CC),   W1M4);
    round_copy<<<W1M4/256, 256>>>((const uint4*)Wp, (uint4*)wp,                 W1M4);
    round_copy<<<W4M4/256, 256>>>((const uint4*)W1, (uint4*)w1,                 W4M4);
    round_copy<<<W4M4/256, 256>>>((const uint4*)W2, (uint4*)w2,                 W4M4);
    bias_concat<<<1, 1024>>>(bq, bk, bv, bqkv);

    // 1) h = LN1(x)  (biased)
    ln_kernel<<<NROWS, 256>>>(x, ln1_w, ln1_b, h);
    // 2) qkv = h @ Wqkv^T + bqkv   (fused, biased out)
    gemm_tf32<0,false,true><<<dim3(QST/BN, NROWS/BM), 256, GEMM_SMEM>>>(h, wqkv, bqkv, nullptr, qkv, NROWS, QST, CC);
    // 3) y = causal-attention(qkv) (into h; biased out)
    attn_mma<<<dim3(BB*HH, TT/128), 256, ATTN_SMEM>>>(qkv, h);
    // 4) x1 = x + y @ Wp^T + bp   (plain)
    gemm_tf32<0,true,false><<<dim3(CC/BN, NROWS/BM), 256, GEMM_SMEM>>>(h, wp, bp, x, x1, NROWS, CC, CC);
    // 5) h2 = LN2(x1)  (biased)
    ln_kernel<<<NROWS, 256>>>(x1, ln2_w, ln2_b, h2);
    // 6) m = gelu(h2 @ W1^T + b1)  (biased)
    gemm_tf32<1,false,true><<<dim3(FF/BN, NROWS/BM), 256, GEMM_SMEM>>>(h2, w1, b1, nullptr, m, NROWS, FF, CC);
    // 7) out = x1 + m @ W2^T + b2  (plain)
    gemm_tf32<0,true,false><<<dim3(CC/BN, NROWS/BM), 256, GEMM_SMEM>>>(m, w2, b2, x1, out, NROWS, CC, FF);
}

// round 7
// speedup vs baseline: 5.8605x; 1.2156x over previous
#include <cuda_runtime.h>
#include <cuda_bf16.h>
#include <math.h>
#include <stdint.h>

// Problem dims (fixed)
#define BB 2
#define TT 2048
#define CC 1024
#define HH 16
#define HD 64
#define NROWS (BB*TT)          // 4096
#define FF (4*CC)              // 4096
#define QST 3072               // fused qkv row stride

// ---------------- scratch (__device__ globals; no allocs allowed) -----------
__device__ float g_h   [NROWS*CC];    // LN1 out (biased bits); later attn y
__device__ float g_qkv [NROWS*QST];   // fused qkv (biased); later h2 (first 4M)
__device__ float g_x1  [NROWS*CC];    // x after attention residual (plain)
__device__ float g_m   [NROWS*FF];    // MLP hidden (biased)

// RNA-to-tf32 equivalent: add half-ulp to fp32 bits; HMMA truncates low 13.
__device__ __forceinline__ float biasbits(float v) {
    return __uint_as_float(__float_as_uint(v) + 0x1000u);
}

// ---------------- LayerNorm (writes biased bits) ----------------
__global__ __launch_bounds__(256)
void ln_kernel(const float* __restrict__ x, const float* __restrict__ w,
               const float* __restrict__ b, float* __restrict__ out)
{
    __shared__ float red[16];
    const int row = blockIdx.x;
    const int t = threadIdx.x;
    const float4* xr = (const float4*)(x + (size_t)row * CC);
    float4 v = xr[t];
    float s  = v.x + v.y + v.z + v.w;
    float ss = v.x*v.x + v.y*v.y + v.z*v.z + v.w*v.w;
    #pragma unroll
    for (int off = 16; off >= 1; off >>= 1) {
        s  += __shfl_xor_sync(0xffffffffu, s,  off);
        ss += __shfl_xor_sync(0xffffffffu, ss, off);
    }
    const int wid = t >> 5, lane = t & 31;
    if (lane == 0) { red[wid] = s; red[8 + wid] = ss; }
    __syncthreads();
    if (t == 0) {
        float S = 0.f, SS = 0.f;
        #pragma unroll
        for (int i = 0; i < 8; i++) { S += red[i]; SS += red[8 + i]; }
        red[0] = S; red[1] = SS;
    }
    __syncthreads();
    const float mu  = red[0] * (1.0f / CC);
    const float var = red[1] * (1.0f / CC) - mu * mu;
    const float rstd = rsqrtf(var + 1e-5f);
    const float4 wv = ((const float4*)w)[t];
    const float4 bv = ((const float4*)b)[t];
    float4 o;
    o.x = biasbits((v.x - mu) * rstd * wv.x + bv.x);
    o.y = biasbits((v.y - mu) * rstd * wv.y + bv.y);
    o.z = biasbits((v.z - mu) * rstd * wv.z + bv.z);
    o.w = biasbits((v.w - mu) * rstd * wv.w + bv.w);
    ((float4*)(out + (size_t)row * CC))[t] = o;
}

// ---------------- helpers ----------------
__device__ __forceinline__ float gelu_exact(float v) {
    return 0.5f * v * (1.0f + erff(v * 0.70710678118654752f));
}
__device__ __forceinline__ void mma16x8x8(float c[4], const uint32_t a[4], const uint32_t b[2]) {
    asm volatile("mma.sync.aligned.m16n8k8.row.col.f32.tf32.tf32.f32 "
        "{%0,%1,%2,%3}, {%4,%5,%6,%7}, {%8,%9}, {%0,%1,%2,%3};\n"
        : "+f"(c[0]), "+f"(c[1]), "+f"(c[2]), "+f"(c[3])
        : "r"(a[0]), "r"(a[1]), "r"(a[2]), "r"(a[3]), "r"(b[0]), "r"(b[1]));
}
__device__ __forceinline__ void cp16(uint32_t s, const float* g) {
    asm volatile("cp.async.ca.shared.global [%0], [%1], 16;\n" :: "r"(s), "l"(g));
}
__device__ __forceinline__ void ldsm4(uint32_t r[4], uint32_t addr) {
    asm volatile("ldmatrix.sync.aligned.m8n8.x4.shared.b16 {%0,%1,%2,%3}, [%4];\n"
        : "=r"(r[0]), "=r"(r[1]), "=r"(r[2]), "=r"(r[3]) : "r"(addr));
}

// ---------------- tf32 tensor-core GEMM core (ldmatrix fragments) -----------
#define BM 128
#define BN 128
#define BK 16
#define LDSK 20
#define GEMM_SMEM (2 * 2 * BM * LDSK * 4)   // 40960 bytes

template<int ACT, bool RES, bool ROUND>
__device__ __forceinline__ void gemm_core(
    const float* __restrict__ A, const float* __restrict__ W,
    const float* __restrict__ bias, const float* __restrict__ res,
    float* __restrict__ out, int K, int ldC,
    int m0, int n0w, int c0, float* gsm)
{
    const int t = threadIdx.x;
    const int wid  = t >> 5;
    const int lane = t & 31;
    const int g    = lane >> 2;
    const int tig  = lane & 3;
    const int wm = (wid & 1) * 64;
    const int wn = (wid >> 1) * 32;

    const uint32_t smA = (uint32_t)__cvta_generic_to_shared(gsm);
    const uint32_t smB = smA + 2 * BM * LDSK * 4;
    const uint32_t stgbytes = BM * LDSK * 4;

    // loader lanes
    const int lr = t >> 1;
    const int kh = (t & 1) * 8;
    const float* ag = A + (size_t)(m0 + lr) * K + kh;
    const float* bg = W + (size_t)(n0w + lr) * K + kh;
    const uint32_t as_s = smA + (lr * LDSK + kh) * 4;
    const uint32_t bs_s = smB + (lr * LDSK + kh) * 4;

    // ldmatrix lane offsets (bytes)
    const uint32_t laneA = (uint32_t)(((lane & 15) * LDSK + 4 * (lane >> 4)) * 4);
    const uint32_t laneB = (uint32_t)((((lane >> 4) * 8 + (lane & 7)) * LDSK + 4 * ((lane >> 3) & 1)) * 4);
    const uint32_t aFragBase = smA + (uint32_t)(wm * LDSK * 4) + laneA;
    const uint32_t bFragBase = smB + (uint32_t)(wn * LDSK * 4) + laneB;

    float acc[4][4][4];
    #pragma unroll
    for (int mt = 0; mt < 4; mt++)
        #pragma unroll
        for (int nt = 0; nt < 4; nt++)
            #pragma unroll
            for (int r = 0; r < 4; r++) acc[mt][nt][r] = 0.f;

    const int KT = K / BK;
    cp16(as_s, ag);      cp16(as_s + 16, ag + 4);
    cp16(bs_s, bg);      cp16(bs_s + 16, bg + 4);
    asm volatile("cp.async.commit_group;\n");

    for (int kt = 0; kt < KT; ++kt) {
        if (kt + 1 < KT) {
            const float* ag2 = ag + (size_t)(kt + 1) * BK;
            const float* bg2 = bg + (size_t)(kt + 1) * BK;
            const uint32_t off = ((kt + 1) & 1) * stgbytes;
            cp16(as_s + off, ag2);  cp16(as_s + off + 16, ag2 + 4);
            cp16(bs_s + off, bg2);  cp16(bs_s + off + 16, bg2 + 4);
            asm volatile("cp.async.commit_group;\n");
            asm volatile("cp.async.wait_group 1;\n");
        } else {
            asm volatile("cp.async.wait_group 0;\n");
        }
        __syncthreads();

        const uint32_t abuf = aFragBase + (kt & 1) * stgbytes;
        const uint32_t bbuf = bFragBase + (kt & 1) * stgbytes;

        uint32_t af[2][4][4];   // [ks][mt][reg]
        uint32_t bf[2][2][4];   // [ks][np][reg]  (np covers nt=2np,2np+1)
        #pragma unroll
        for (int ks = 0; ks < 2; ++ks) {
            #pragma unroll
            for (int mt = 0; mt < 4; ++mt)
                ldsm4(af[ks][mt], abuf + (uint32_t)(mt * 16 * LDSK * 4) + ks * 32);
            #pragma unroll
            for (int np = 0; np < 2; ++np)
                ldsm4(bf[ks][np], bbuf + (uint32_t)(np * 16 * LDSK * 4) + ks * 32);
        }
        // RNA-round the weight fragments in-register (half-ulp bump)
        #pragma unroll
        for (int ks = 0; ks < 2; ++ks)
            #pragma unroll
            for (int np = 0; np < 2; ++np)
                #pragma unroll
                for (int r = 0; r < 4; ++r) bf[ks][np][r] += 0x1000u;

        #pragma unroll
        for (int ks = 0; ks < 2; ++ks)
            #pragma unroll
            for (int mt = 0; mt < 4; ++mt)
                #pragma unroll
                for (int np = 0; np < 2; ++np) {
                    mma16x8x8(acc[mt][2*np],   af[ks][mt], &bf[ks][np][0]);
                    mma16x8x8(acc[mt][2*np+1], af[ks][mt], &bf[ks][np][2]);
                }
        __syncthreads();
    }

    #pragma unroll
    for (int nt = 0; nt < 4; ++nt) {
        const int nloc = wn + nt * 8 + 2 * tig;
        const int col  = c0 + nloc;
        const float2 bc = *(const float2*)(bias + n0w + nloc);
        #pragma unroll
        for (int mt = 0; mt < 4; ++mt) {
            const int row = m0 + wm + mt * 16 + g;
            float v0 = acc[mt][nt][0] + bc.x;
            float v1 = acc[mt][nt][1] + bc.y;
            float v2 = acc[mt][nt][2] + bc.x;
            float v3 = acc[mt][nt][3] + bc.y;
            if (ACT == 1) {
                v0 = gelu_exact(v0); v1 = gelu_exact(v1);
                v2 = gelu_exact(v2); v3 = gelu_exact(v3);
            }
            if (RES) {
                const float2 r0 = *(const float2*)(res + (size_t)row * ldC + col);
                const float2 r1 = *(const float2*)(res + (size_t)(row + 8) * ldC + col);
                v0 += r0.x; v1 += r0.y; v2 += r1.x; v3 += r1.y;
            }
            if (ROUND) {
                v0 = biasbits(v0); v1 = biasbits(v1);
                v2 = biasbits(v2); v3 = biasbits(v3);
            }
            *(float2*)(out + (size_t)row * ldC + col)       = make_float2(v0, v1);
            *(float2*)(out + (size_t)(row + 8) * ldC + col) = make_float2(v2, v3);
        }
    }
}

template<int ACT, bool RES, bool ROUND>
__global__ __launch_bounds__(256, 2)
void gemm3(const float* __restrict__ A, const float* __restrict__ W,
           const float* __restrict__ bias, const float* __restrict__ res,
           float* __restrict__ out, int K, int ldC)
{
    extern __shared__ float gsm[];
    gemm_core<ACT, RES, ROUND>(A, W, bias, res, out, K, ldC,
                               blockIdx.y * BM, blockIdx.x * BN, blockIdx.x * BN, gsm);
}

// fused QKV: grid.x = 24 tiles; tiles 0-7 -> Wq, 8-15 -> Wk, 16-23 -> Wv
__global__ __launch_bounds__(256, 2)
void gemm3_qkv(const float* __restrict__ A,
               const float* __restrict__ Wq, const float* __restrict__ Wk,
               const float* __restrict__ Wv,
               const float* __restrict__ bq, const float* __restrict__ bk,
               const float* __restrict__ bv,
               float* __restrict__ out)
{
    extern __shared__ float gsm[];
    const int tile = blockIdx.x;
    const int sel = tile >> 3;
    const float* W = (sel == 0) ? Wq : (sel == 1) ? Wk : Wv;
    const float* b = (sel == 0) ? bq : (sel == 1) ? bk : bv;
    gemm_core<0, false, true>(A, W, b, nullptr, out, CC, QST,
                              blockIdx.y * BM, (tile & 7) * BN, tile * BN, gsm);
}

// ---------------- Flash attention, tf32 tensor cores ------------------------
// BQ=128 (8 warps x m16), BKV=64, HD=64. qkv fused [rows][3072], pre-biased.
#define ATS 68
#define ATTN_SMEM ((128*ATS + 64*ATS + 128*ATS) * 4)   // 87040 bytes

__global__ __launch_bounds__(256, 2)
void attn_mma(const float* __restrict__ qkv, float* __restrict__ y)
{
    extern __shared__ uint32_t smu[];
    uint32_t* Qs  = smu;                       // [128][ATS]
    uint32_t* KVs = smu + 128 * ATS;           // [64][ATS]  (K then V)
    uint32_t* Ps  = smu + (128 + 64) * ATS;    // [128][ATS]

    const int bh = blockIdx.x;
    const int b  = bh >> 4;
    const int h  = bh & 15;
    const int it = (int)gridDim.y - 1 - blockIdx.y;
    const int t  = threadIdx.x;
    const int wid  = t >> 5;
    const int lane = t & 31;
    const int g    = lane >> 2;
    const int tig  = lane & 3;
    const int wm = wid * 16;

    // Q tile raw copy (biased bits); 1/8 scale folded into exp args
    #pragma unroll
    for (int j = 0; j < 8; ++j) {
        const int fid = t + j * 256;
        const int row = fid >> 4;
        const int d4  = (fid & 15) * 4;
        *(uint4*)&Qs[row * ATS + d4] =
            *(const uint4*)(qkv + (size_t)(b * TT + it * 128 + row) * QST + h * HD + d4);
    }

    float oc[8][4];
    #pragma unroll
    for (int nt = 0; nt < 8; ++nt)
        #pragma unroll
        for (int r = 0; r < 4; ++r) oc[nt][r] = 0.f;
    float m0 = -INFINITY, m1 = -INFINITY, l0 = 0.f, l1 = 0.f;

    const int JT = 2 * it + 2;
    for (int jt = 0; jt < JT; ++jt) {
        __syncthreads();
        #pragma unroll
        for (int j = 0; j < 4; ++j) {
            const int fid = t + j * 256;
            const int row = fid >> 4;
            const int d4  = (fid & 15) * 4;
            *(uint4*)&KVs[row * ATS + d4] =
                *(const uint4*)(qkv + (size_t)(b * TT + jt * 64 + row) * QST + CC + h * HD + d4);
        }
        __syncthreads();

        float sc[8][4];
        #pragma unroll
        for (int nt = 0; nt < 8; ++nt)
            #pragma unroll
            for (int r = 0; r < 4; ++r) sc[nt][r] = 0.f;
        #pragma unroll
        for (int ks = 0; ks < 8; ++ks) {
            const int base = (wm + g) * ATS + ks * 8 + tig;
            uint32_t a[4];
            a[0] = Qs[base];            a[1] = Qs[base + 8 * ATS];
            a[2] = Qs[base + 4];        a[3] = Qs[base + 8 * ATS + 4];
            #pragma unroll
            for (int nt = 0; nt < 8; ++nt) {
                uint32_t bb[2];
                bb[0] = KVs[(nt * 8 + g) * ATS + ks * 8 + tig];
                bb[1] = KVs[(nt * 8 + g) * ATS + ks * 8 + tig + 4];
                mma16x8x8(sc[nt], a, bb);
            }
        }

        if (jt >= 2 * it) {
            const int r0 = it * 128 + wm + g;
            const int r1 = r0 + 8;
            const int cb = jt * 64 + 2 * tig;
            #pragma unroll
            for (int nt = 0; nt < 8; ++nt) {
                const int c0 = cb + nt * 8;
                if (c0     > r0) sc[nt][0] = -1e30f;
                if (c0 + 1 > r0) sc[nt][1] = -1e30f;
                if (c0     > r1) sc[nt][2] = -1e30f;
                if (c0 + 1 > r1) sc[nt][3] = -1e30f;
            }
        }

        float mx0 = -INFINITY, mx1 = -INFINITY;
        #pragma unroll
        for (int nt = 0; nt < 8; ++nt) {
            mx0 = fmaxf(mx0, fmaxf(sc[nt][0], sc[nt][1]));
            mx1 = fmaxf(mx1, fmaxf(sc[nt][2], sc[nt][3]));
        }
        mx0 = fmaxf(mx0, __shfl_xor_sync(0xffffffffu, mx0, 1));
        mx0 = fmaxf(mx0, __shfl_xor_sync(0xffffffffu, mx0, 2));
        mx1 = fmaxf(mx1, __shfl_xor_sync(0xffffffffu, mx1, 1));
        mx1 = fmaxf(mx1, __shfl_xor_sync(0xffffffffu, mx1, 2));
        const float mn0 = fmaxf(m0, mx0), mn1 = fmaxf(m1, mx1);
        const float cr0 = __expf((m0 - mn0) * 0.125f);
        const float cr1 = __expf((m1 - mn1) * 0.125f);
        m0 = mn0; m1 = mn1;
        float s0 = 0.f, s1 = 0.f;
        #pragma unroll
        for (int nt = 0; nt < 8; ++nt) {
            sc[nt][0] = __expf((sc[nt][0] - mn0) * 0.125f);
            sc[nt][1] = __expf((sc[nt][1] - mn0) * 0.125f);
            sc[nt][2] = __expf((sc[nt][2] - mn1) * 0.125f);
            sc[nt][3] = __expf((sc[nt][3] - mn1) * 0.125f);
            s0 += sc[nt][0] + sc[nt][1];
            s1 += sc[nt][2] + sc[nt][3];
            uint2 p01, p23;
            p01.x = __float_as_uint(sc[nt][0]) + 0x1000u;
            p01.y = __float_as_uint(sc[nt][1]) + 0x1000u;
            p23.x = __float_as_uint(sc[nt][2]) + 0x1000u;
            p23.y = __float_as_uint(sc[nt][3]) + 0x1000u;
            *(uint2*)&Ps[(wm + g) * ATS + nt * 8 + 2 * tig]     = p01;
            *(uint2*)&Ps[(wm + g + 8) * ATS + nt * 8 + 2 * tig] = p23;
        }
        s0 += __shfl_xor_sync(0xffffffffu, s0, 1);
        s0 += __shfl_xor_sync(0xffffffffu, s0, 2);
        s1 += __shfl_xor_sync(0xffffffffu, s1, 1);
        s1 += __shfl_xor_sync(0xffffffffu, s1, 2);
        l0 = l0 * cr0 + s0;
        l1 = l1 * cr1 + s1;
        #pragma unroll
        for (int nt = 0; nt < 8; ++nt) {
            oc[nt][0] *= cr0; oc[nt][1] *= cr0;
            oc[nt][2] *= cr1; oc[nt][3] *= cr1;
        }
        __syncthreads();

        #pragma unroll
        for (int j = 0; j < 4; ++j) {
            const int fid = t + j * 256;
            const int row = fid >> 4;
            const int d4  = (fid & 15) * 4;
            *(uint4*)&KVs[row * ATS + d4] =
                *(const uint4*)(qkv + (size_t)(b * TT + jt * 64 + row) * QST + 2 * CC + h * HD + d4);
        }
        __syncthreads();

        #pragma unroll
        for (int ks = 0; ks < 8; ++ks) {
            const int base = (wm + g) * ATS + ks * 8 + tig;
            uint32_t a[4];
            a[0] = Ps[base];            a[1] = Ps[base + 8 * ATS];
            a[2] = Ps[base + 4];        a[3] = Ps[base + 8 * ATS + 4];
            #pragma unroll
            for (int nt = 0; nt < 8; ++nt) {
                uint32_t bb[2];
                bb[0] = KVs[(ks * 8 + tig) * ATS + nt * 8 + g];
                bb[1] = KVs[(ks * 8 + tig + 4) * ATS + nt * 8 + g];
                mma16x8x8(oc[nt], a, bb);
            }
        }
    }

    const float inv0 = 1.0f / l0, inv1 = 1.0f / l1;
    const size_t r0 = (size_t)(b * TT + it * 128 + wm + g);
    #pragma unroll
    for (int nt = 0; nt < 8; ++nt) {
        const int col = h * HD + nt * 8 + 2 * tig;
        *(float2*)(y + r0 * CC + col) =
            make_float2(biasbits(oc[nt][0] * inv0), biasbits(oc[nt][1] * inv0));
        *(float2*)(y + (r0 + 8) * CC + col) =
            make_float2(biasbits(oc[nt][2] * inv1), biasbits(oc[nt][3] * inv1));
    }
}

// ---------------- launch ----------------
extern "C" void kernel_launch(void* const* d_in, const int* in_sizes, int n_in,
                              void* d_out, int out_size)
{
    (void)in_sizes; (void)n_in; (void)out_size;
    const float* x     = (const float*)d_in[0];
    const float* ln1_w = (const float*)d_in[1];
    const float* ln1_b = (const float*)d_in[2];
    const float* ln2_w = (const float*)d_in[3];
    const float* ln2_b = (const float*)d_in[4];
    const float* Wq    = (const float*)d_in[5];
    const float* bq    = (const float*)d_in[6];
    const float* Wk    = (const float*)d_in[7];
    const float* bk    = (const float*)d_in[8];
    const float* Wv    = (const float*)d_in[9];
    const float* bv    = (const float*)d_in[10];
    const float* Wp    = (const float*)d_in[11];
    const float* bp    = (const float*)d_in[12];
    const float* W1    = (const float*)d_in[13];
    const float* b1    = (const float*)d_in[14];
    const float* W2    = (const float*)d_in[15];
    const float* b2    = (const float*)d_in[16];
    float* out = (float*)d_out;

    float *h, *qkv, *x1, *m;
    cudaGetSymbolAddress((void**)&h,   g_h);
    cudaGetSymbolAddress((void**)&qkv, g_qkv);
    cudaGetSymbolAddress((void**)&x1,  g_x1);
    cudaGetSymbolAddress((void**)&m,   g_m);
    float* h2 = qkv;   // reuse: qkv dead after attention

    cudaFuncSetAttribute(gemm3_qkv,           cudaFuncAttributeMaxDynamicSharedMemorySize, GEMM_SMEM);
    cudaFuncSetAttribute(gemm3<0,true ,false>, cudaFuncAttributeMaxDynamicSharedMemorySize, GEMM_SMEM);
    cudaFuncSetAttribute(gemm3<1,false,true >, cudaFuncAttributeMaxDynamicSharedMemorySize, GEMM_SMEM);
    cudaFuncSetAttribute(attn_mma, cudaFuncAttributeMaxDynamicSharedMemorySize, ATTN_SMEM);

    // 1) h = LN1(x)  (biased)
    ln_kernel<<<NROWS, 256>>>(x, ln1_w, ln1_b, h);
    // 2) qkv = h @ [Wq|Wk|Wv]^T + b   (one launch, biased out)
    gemm3_qkv<<<dim3(QST/BN, NROWS/BM), 256, GEMM_SMEM>>>(h, Wq, Wk, Wv, bq, bk, bv, qkv);
    // 3) y = causal-attention(qkv) (into h; biased out)
    attn_mma<<<dim3(BB*HH, TT/128), 256, ATTN_SMEM>>>(qkv, h);
    // 4) x1 = x + y @ Wp^T + bp   (plain)
    gemm3<0,true,false><<<dim3(CC/BN, NROWS/BM), 256, GEMM_SMEM>>>(h, Wp, bp, x, x1, CC, CC);
    // 5) h2 = LN2(x1)  (biased)
    ln_kernel<<<NROWS, 256>>>(x1, ln2_w, ln2_b, h2);
    // 6) m = gelu(h2 @ W1^T + b1)  (biased)
    gemm3<1,false,true><<<dim3(FF/BN, NROWS/BM), 256, GEMM_SMEM>>>(h2, W1, b1, nullptr, m, CC, FF);
    // 7) out = x1 + m @ W2^T + b2  (plain)
    gemm3<0,true,false><<<dim3(CC/BN, NROWS/BM), 256, GEMM_SMEM>>>(m, W2, b2, x1, out, FF, CC);
}